// round 8
// baseline (speedup 1.0000x reference)
#include <cuda_runtime.h>
#include <math.h>

#define BB   128   // batch
#define TSEQ 512   // sequence length
#define DD   256   // model dim
#define HH   256   // lstm hidden
#define NG   1024  // 4*HH
#define NBLK 96    // persistent LSTM grid: 6 layer-steps x 16 col-tiles
#define ADP  260   // sAd pitch (floats): 256 dup + 4 pad, 16B-aligned rows

typedef unsigned long long u64;

// ---- packed f32x2 helpers ----
__device__ __forceinline__ u64 pk2(float lo, float hi) {
    u64 r; asm("mov.b64 %0, {%1,%2};" : "=l"(r) : "f"(lo), "f"(hi)); return r;
}
__device__ __forceinline__ u64 ff2(u64 a, u64 b, u64 c) {
    u64 d; asm("fma.rn.f32x2 %0, %1, %2, %3;" : "=l"(d) : "l"(a), "l"(b), "l"(c));
    return d;
}
__device__ __forceinline__ float2 up2(u64 v) {
    float2 f; asm("mov.b64 {%0,%1}, %2;" : "=f"(f.x), "=f"(f.y) : "l"(v)); return f;
}

// ---------------- device scratch ----------------
__device__ float g_x[BB * TSEQ * DD];
__device__ float g_feats[BB * TSEQ * DD];
__device__ float g_Wt[2 * 3 * 512 * NG];       // [dl][k(512)][col*4+gate]
__device__ float g_cur[2 * 2 * 2 * BB * DD];   // [dir][stage][parity][b][d]
__device__ float g_h[2 * 3 * 2 * BB * HH];     // [dl][pingpong][b][h]
__device__ float g_c[2 * 3 * BB * HH];
__device__ unsigned g_sync;

// ---------------- embedding gather ----------------
__global__ void k_embed(const int* __restrict__ tokens, const float* __restrict__ E) {
    int row = blockIdx.x;
    int tok = tokens[row];
    const float4* src = reinterpret_cast<const float4*>(E) + (size_t)tok * (DD / 4);
    float4* dst = reinterpret_cast<float4*>(g_x) + (size_t)row * (DD / 4);
    dst[threadIdx.x] = src[threadIdx.x];
}

// ---------------- conv bank (FFMA2, pre-paired x) — unchanged ----------------
__global__ void __launch_bounds__(256, 2) k_conv(
    const float* __restrict__ W3, const float* __restrict__ W5,
    const float* __restrict__ W7, const float* __restrict__ bconv, int iter)
{
    const int o  = threadIdx.x;
    const int t0 = blockIdx.x * 16;
    const int b  = blockIdx.y;

    __shared__ u64 sxp[DD][15];
    const float* xb = g_x + (size_t)b * TSEQ * DD;
    float xr[22];
#pragma unroll
    for (int r = 0; r < 22; ++r) {
        int tg = t0 - 3 + r;
        xr[r] = (tg >= 0 && tg < TSEQ) ? xb[(size_t)tg * DD + o] : 0.f;
    }
#pragma unroll
    for (int i = 0; i < 14; ++i) sxp[o][i] = pk2(xr[i], xr[i + 8]);
    __syncthreads();

    u64 acc3[8], acc5[8], acc7[8];
    const u64 z = pk2(0.f, 0.f);
#pragma unroll
    for (int i = 0; i < 8; ++i) { acc3[i] = z; acc5[i] = z; acc7[i] = z; }

    const float* W3i = W3 + (size_t)iter * 3 * DD * DD + o;
    const float* W5i = W5 + (size_t)iter * 5 * DD * DD + o;
    const float* W7i = W7 + (size_t)iter * 7 * DD * DD + o;

    for (int c = 0; c < DD; ++c) {
        u64 xp[14];
#pragma unroll
        for (int i = 0; i < 14; ++i) xp[i] = sxp[c][i];

#pragma unroll
        for (int k = 0; k < 7; ++k) {
            float w = W7i[((size_t)k * DD + c) * DD];
            u64 ww = pk2(w, w);
#pragma unroll
            for (int i = 0; i < 8; ++i) acc7[i] = ff2(xp[i + k], ww, acc7[i]);
        }
#pragma unroll
        for (int k = 0; k < 5; ++k) {
            float w = W5i[((size_t)k * DD + c) * DD];
            u64 ww = pk2(w, w);
#pragma unroll
            for (int i = 0; i < 8; ++i) acc5[i] = ff2(xp[i + k + 1], ww, acc5[i]);
        }
#pragma unroll
        for (int k = 0; k < 3; ++k) {
            float w = W3i[((size_t)k * DD + c) * DD];
            u64 ww = pk2(w, w);
#pragma unroll
            for (int i = 0; i < 8; ++i) acc3[i] = ff2(xp[i + k + 2], ww, acc3[i]);
        }
    }

    float b3 = bconv[(iter * 3 + 0) * DD + o];
    float b5 = bconv[(iter * 3 + 1) * DD + o];
    float b7 = bconv[(iter * 3 + 2) * DD + o];
    float* fb = g_feats + ((size_t)b * TSEQ + t0) * DD + o;
#pragma unroll
    for (int i = 0; i < 8; ++i) {
        float2 a3 = up2(acc3[i]), a5 = up2(acc5[i]), a7 = up2(acc7[i]);
        float2 res = up2(sxp[o][i + 3]);
        fb[(size_t)i * DD] = tanhf(a3.x + b3) + tanhf(a5.x + b5) +
                             tanhf(a7.x + b7) + res.x;
        fb[(size_t)(i + 8) * DD] = tanhf(a3.y + b3) + tanhf(a5.y + b5) +
                                   tanhf(a7.y + b7) + res.y;
    }
}

// ---------------- layernorm ----------------
__global__ void k_ln(const float* __restrict__ gamma, const float* __restrict__ beta, int iter) {
    int wid = threadIdx.x >> 5, lane = threadIdx.x & 31;
    int row = blockIdx.x * 8 + wid;
    const float4* f = reinterpret_cast<const float4*>(g_feats + (size_t)row * DD);
    float4 v0 = f[lane];
    float4 v1 = f[32 + lane];
    float s = v0.x + v0.y + v0.z + v0.w + v1.x + v1.y + v1.z + v1.w;
    float q = v0.x*v0.x + v0.y*v0.y + v0.z*v0.z + v0.w*v0.w +
              v1.x*v1.x + v1.y*v1.y + v1.z*v1.z + v1.w*v1.w;
#pragma unroll
    for (int ofs = 16; ofs; ofs >>= 1) {
        s += __shfl_xor_sync(0xffffffffu, s, ofs);
        q += __shfl_xor_sync(0xffffffffu, q, ofs);
    }
    float mean = s * (1.f / 256.f);
    float var  = q * (1.f / 256.f) - mean * mean;
    float rstd = rsqrtf(var + 1e-3f);

    const float* ga = gamma + iter * DD;
    const float* be = beta + iter * DD;
    float4* xo = reinterpret_cast<float4*>(g_x + (size_t)row * DD);
    int c0 = lane * 4;
    float4 r0, r1;
    r0.x = (v0.x - mean) * rstd * ga[c0 + 0] + be[c0 + 0];
    r0.y = (v0.y - mean) * rstd * ga[c0 + 1] + be[c0 + 1];
    r0.z = (v0.z - mean) * rstd * ga[c0 + 2] + be[c0 + 2];
    r0.w = (v0.w - mean) * rstd * ga[c0 + 3] + be[c0 + 3];
    r1.x = (v1.x - mean) * rstd * ga[128 + c0 + 0] + be[128 + c0 + 0];
    r1.y = (v1.y - mean) * rstd * ga[128 + c0 + 1] + be[128 + c0 + 1];
    r1.z = (v1.z - mean) * rstd * ga[128 + c0 + 2] + be[128 + c0 + 2];
    r1.w = (v1.w - mean) * rstd * ga[128 + c0 + 3] + be[128 + c0 + 3];
    xo[lane] = r0;
    xo[32 + lane] = r1;
}

// ---------------- weight pre-transpose: [dl][k][col*4+g] ----------------
__global__ void k_transpose(const float* __restrict__ Wx, const float* __restrict__ Wh) {
    int idx = blockIdx.x * 256 + threadIdx.x;
    if (idx >= 2 * 3 * 512 * NG) return;
    int dl  = idx / (512 * NG);
    int rem = idx % (512 * NG);
    int k   = rem / NG;
    int cp  = rem % NG;
    int col = cp >> 2, g = cp & 3;
    int n = g * 256 + col;
    float v = (k < 256) ? Wx[(size_t)dl * 256 * NG + (size_t)k * NG + n]
                        : Wh[(size_t)dl * 256 * NG + (size_t)(k - 256) * NG + n];
    g_Wt[idx] = v;
}

__global__ void k_zero() {
    int i = blockIdx.x * 256 + threadIdx.x;
    if (i < 2 * 3 * 2 * BB * HH) g_h[i] = 0.f;
    if (i < 2 * 3 * BB * HH)     g_c[i] = 0.f;
    if (i == 0) g_sync = 0u;
}

// ---------------- persistent wavefront LSTM -------------------------------
// 96 blocks x 512 threads (4 warps/SMSP). Block: 128m x 16 cols (x4 gates).
// W slice 512x64 = 128KB resident in smem. A staged DUPLICATED (gate-paired
// FFMA2 loop: 2 LDS.128(A) + 1 LDS.128(W) + 8 FFMA2 = 11 issues / 16 pipe-cyc).
// c state in registers; residual prefetched; 32-k double-buffered chunks.
__global__ void __launch_bounds__(512, 1) k_lstm_persist(
    const float* __restrict__ blstm, float* __restrict__ out)
{
    extern __shared__ float smem[];
    float* sWr = smem;                         // [512][64]      128 KB
    float* sAd = smem + 512 * 64;              // [2][32][ADP]   66.6 KB (dup A)

    const int bx    = blockIdx.x;
    const int ls    = bx >> 4;            // 0..5
    const int dir   = ls & 1;
    const int layer = ls >> 1;
    const int sub   = bx & 15;
    const int j0    = sub * 16;           // col tile base (16 cols)
    const int tid   = threadIdx.x;
    const int jc    = tid & 15;           // col within tile
    const int mg    = tid >> 4;           // 0..31 -> 4 m-rows each
    const int dl    = dir * 3 + layer;

    // ---- load W slice into smem once ----
    {
        const float4* src = reinterpret_cast<const float4*>(
            g_Wt + (size_t)dl * 512 * NG);
        float4* dst = reinterpret_cast<float4*>(sWr);
        for (int i = tid; i < 512 * 16; i += 512) {
            int k = i >> 4, q = i & 15;
            dst[k * 16 + q] = src[(size_t)k * 256 + j0 + q];
        }
    }

    const int col = j0 + jc;
    const float* bbias = blstm + (size_t)dl * NG;
    const float bi  = bbias[col];
    const float bf_ = bbias[256 + col];
    const float bg  = bbias[512 + col];
    const float bo  = bbias[768 + col];

    // c state in registers (block-private across the whole sequence)
    float creg[4] = {0.f, 0.f, 0.f, 0.f};

    // A-fill roles: warp-constant k => conflict-free dup STS.64
    const int ftm = tid & 127;            // m row (0..127)
    const int fko = (tid >> 7) * 8;       // k base within chunk (0,8,16,24)

    const unsigned nb = gridDim.x;
    const int lprev = (layer > 0) ? (layer - 1) : 0;

    for (int w = 0; w < TSEQ + 2; ++w) {
        const int t = w - layer;
        if (t >= 0 && t < TSEQ) {
            const int tt = dir ? (TSEQ - 1 - t) : t;
            const int rp = t & 1, wp = rp ^ 1;
            const float* hin = g_h + (size_t)(dl * 2 + rp) * BB * HH;
            const float* cursrc = g_cur +
                (size_t)((dir * 2 + lprev) * 2 + (t & 1)) * BB * DD;
            float* curdst = g_cur +
                (size_t)((dir * 2 + layer) * 2 + (t & 1)) * BB * DD;

            // prefetch residual inputs for epilogue (hidden under GEMM)
            float ainv[4];
#pragma unroll
            for (int mi = 0; mi < 4; ++mi) {
                int m = mg * 4 + mi;
                ainv[mi] = (layer == 0)
                    ? g_x[((size_t)m * TSEQ + tt) * DD + col]
                    : __ldcg(cursrc + (size_t)m * DD + col);
            }

            u64 acc[4][2];                 // [mi][gatepair: (i,f),(g,o)]
            const u64 zz = pk2(0.f, 0.f);
#pragma unroll
            for (int mi = 0; mi < 4; ++mi) { acc[mi][0] = zz; acc[mi][1] = zz; }

            // prefetch chunk 0 (this thread: row ftm, k fko..fko+7)
            float4 va0, va1;
            {
                const float* src = (layer == 0)
                    ? (g_x + ((size_t)ftm * TSEQ + tt) * DD + fko)
                    : (cursrc + (size_t)ftm * DD + fko);
                va0 = *reinterpret_cast<const float4*>(src);
                va1 = *reinterpret_cast<const float4*>(src + 4);
            }
            // stage chunk 0 (duplicated)
            {
                float* db = sAd;
                *reinterpret_cast<u64*>(&db[(fko+0)*ADP + ftm*2]) = pk2(va0.x, va0.x);
                *reinterpret_cast<u64*>(&db[(fko+1)*ADP + ftm*2]) = pk2(va0.y, va0.y);
                *reinterpret_cast<u64*>(&db[(fko+2)*ADP + ftm*2]) = pk2(va0.z, va0.z);
                *reinterpret_cast<u64*>(&db[(fko+3)*ADP + ftm*2]) = pk2(va0.w, va0.w);
                *reinterpret_cast<u64*>(&db[(fko+4)*ADP + ftm*2]) = pk2(va1.x, va1.x);
                *reinterpret_cast<u64*>(&db[(fko+5)*ADP + ftm*2]) = pk2(va1.y, va1.y);
                *reinterpret_cast<u64*>(&db[(fko+6)*ADP + ftm*2]) = pk2(va1.z, va1.z);
                *reinterpret_cast<u64*>(&db[(fko+7)*ADP + ftm*2]) = pk2(va1.w, va1.w);
            }
            __syncthreads();

            for (int ci = 0; ci < 16; ++ci) {
                // prefetch next chunk into regs
                if (ci < 15) {
                    int kk = (ci + 1) * 32 + fko;
                    if (kk < 256) {
                        const float* src = (layer == 0)
                            ? (g_x + ((size_t)ftm * TSEQ + tt) * DD + kk)
                            : (cursrc + (size_t)ftm * DD + kk);
                        va0 = *reinterpret_cast<const float4*>(src);
                        va1 = *reinterpret_cast<const float4*>(src + 4);
                    } else {
                        const float4* src = reinterpret_cast<const float4*>(
                            hin + (size_t)ftm * HH + (kk - 256));
                        va0 = __ldcg(src);
                        va1 = __ldcg(src + 1);
                    }
                }

                // compute current chunk: 11 issues / 16 FMA-pipe cyc per k
                const float* ab = sAd + (ci & 1) * (32 * ADP) + mg * 8;
                const float* wb = sWr + (size_t)ci * 32 * 64 + jc * 4;
#pragma unroll
                for (int k = 0; k < 32; ++k) {
                    ulonglong2 aa = *reinterpret_cast<const ulonglong2*>(ab + k * ADP);
                    ulonglong2 ab2 = *reinterpret_cast<const ulonglong2*>(ab + k * ADP + 4);
                    ulonglong2 wv = *reinterpret_cast<const ulonglong2*>(wb + k * 64);
                    acc[0][0] = ff2(aa.x,  wv.x, acc[0][0]);
                    acc[0][1] = ff2(aa.x,  wv.y, acc[0][1]);
                    acc[1][0] = ff2(aa.y,  wv.x, acc[1][0]);
                    acc[1][1] = ff2(aa.y,  wv.y, acc[1][1]);
                    acc[2][0] = ff2(ab2.x, wv.x, acc[2][0]);
                    acc[2][1] = ff2(ab2.x, wv.y, acc[2][1]);
                    acc[3][0] = ff2(ab2.y, wv.x, acc[3][0]);
                    acc[3][1] = ff2(ab2.y, wv.y, acc[3][1]);
                }

                // stage prefetched chunk into other buffer, then sync
                if (ci < 15) {
                    float* db = sAd + ((ci + 1) & 1) * (32 * ADP);
                    *reinterpret_cast<u64*>(&db[(fko+0)*ADP + ftm*2]) = pk2(va0.x, va0.x);
                    *reinterpret_cast<u64*>(&db[(fko+1)*ADP + ftm*2]) = pk2(va0.y, va0.y);
                    *reinterpret_cast<u64*>(&db[(fko+2)*ADP + ftm*2]) = pk2(va0.z, va0.z);
                    *reinterpret_cast<u64*>(&db[(fko+3)*ADP + ftm*2]) = pk2(va0.w, va0.w);
                    *reinterpret_cast<u64*>(&db[(fko+4)*ADP + ftm*2]) = pk2(va1.x, va1.x);
                    *reinterpret_cast<u64*>(&db[(fko+5)*ADP + ftm*2]) = pk2(va1.y, va1.y);
                    *reinterpret_cast<u64*>(&db[(fko+6)*ADP + ftm*2]) = pk2(va1.z, va1.z);
                    *reinterpret_cast<u64*>(&db[(fko+7)*ADP + ftm*2]) = pk2(va1.w, va1.w);
                    __syncthreads();
                }
            }

            float* hout = g_h + (size_t)(dl * 2 + wp) * BB * HH;
            float* cout = g_c + (size_t)dl * BB * HH;
#pragma unroll
            for (int mi = 0; mi < 4; ++mi) {
                int m = mg * 4 + mi;
                float2 zif = up2(acc[mi][0]);   // (z_i, z_f)
                float2 zgo = up2(acc[mi][1]);   // (z_g, z_o)
                float vzi = zif.x + bi;
                float vzf = zif.y + bf_;
                float vzg = zgo.x + bg;
                float vzo = zgo.y + bo;
                float ig = 1.f / (1.f + expf(-vzi));
                float fg = 1.f / (1.f + expf(-vzf));
                float gg = tanhf(vzg);
                float og = 1.f / (1.f + expf(-vzo));
                float cn = fg * creg[mi] + ig * gg;
                float hn = og * tanhf(cn);
                creg[mi] = cn;
                hout[(size_t)m * HH + col] = hn;
                if (t == TSEQ - 1)
                    cout[(size_t)m * HH + col] = cn;
                float cu = ainv[mi] + hn;
                if (layer == 2)
                    out[((size_t)m * TSEQ + tt) * 512 + dir * 256 + col] = cu;
                else
                    curdst[(size_t)m * DD + col] = cu;
            }
        }

        // ---- grid barrier (proven R3/R6 form) ----
        __syncthreads();
        __threadfence();
        if (tid == 0) {
            atomicAdd(&g_sync, 1u);
            unsigned target = nb * (unsigned)(w + 1);
            while (*(volatile unsigned*)&g_sync < target) __nanosleep(64);
        }
        __syncthreads();
    }
}

// ---------------- final states ----------------
__global__ void k_states(float* __restrict__ out) {
    int idx = blockIdx.x * 256 + threadIdx.x;
    if (idx >= 2 * 3 * BB * HH) return;
    int j  = idx & 255;
    int m  = (idx >> 8) & 127;
    int dl = idx >> 15;
    const size_t SEQ = (size_t)BB * TSEQ * 512;
    const size_t SH  = 2 * 3 * BB * HH;
    out[SEQ + idx]      = g_h[(size_t)(dl * 2 + 0) * BB * HH + (size_t)m * HH + j];
    out[SEQ + SH + idx] = g_c[(size_t)dl * BB * HH + (size_t)m * HH + j];
}

// ---------------- launch ----------------
extern "C" void kernel_launch(void* const* d_in, const int* in_sizes, int n_in,
                              void* d_out, int out_size) {
    const int*   tokens = (const int*)d_in[0];
    const float* E      = (const float*)d_in[1];
    const float* W3     = (const float*)d_in[2];
    const float* W5     = (const float*)d_in[3];
    const float* W7     = (const float*)d_in[4];
    const float* bconv  = (const float*)d_in[5];
    const float* gamma  = (const float*)d_in[6];
    const float* beta   = (const float*)d_in[7];
    const float* Wx     = (const float*)d_in[8];
    const float* Wh     = (const float*)d_in[9];
    const float* blstm  = (const float*)d_in[10];
    float* out = (float*)d_out;

    const int SMEM_BYTES = (512 * 64 + 2 * 32 * ADP) * 4;   // 197,632 B
    cudaFuncSetAttribute(k_lstm_persist,
                         cudaFuncAttributeMaxDynamicSharedMemorySize,
                         SMEM_BYTES);

    k_embed<<<BB * TSEQ, 64>>>(tokens, E);
    for (int it = 0; it < 2; ++it) {
        k_conv<<<dim3(TSEQ / 16, BB), 256>>>(W3, W5, W7, bconv, it);
        k_ln<<<BB * TSEQ / 8, 256>>>(gamma, beta, it);
    }
    k_transpose<<<(2 * 3 * 512 * NG + 255) / 256, 256>>>(Wx, Wh);
    k_zero<<<1536, 256>>>();
    k_lstm_persist<<<NBLK, 512, SMEM_BYTES>>>(blstm, out);
    k_states<<<768, 256>>>(out);
}

// round 11
// speedup vs baseline: 1.5694x; 1.5694x over previous
#include <cuda_runtime.h>
#include <cuda_bf16.h>
#include <math.h>
#include <cstdint>

#define BB   128
#define TSEQ 512
#define DD   256
#define HH   256
#define NG   1024
#define NBLK 96
#define APITCH 130

typedef unsigned long long u64;
typedef unsigned int u32;

// ---- packed f32x2 helpers ----
__device__ __forceinline__ u64 pk2(float lo, float hi) {
    u64 r; asm("mov.b64 %0, {%1,%2};" : "=l"(r) : "f"(lo), "f"(hi)); return r;
}
__device__ __forceinline__ u64 ff2(u64 a, u64 b, u64 c) {
    u64 d; asm("fma.rn.f32x2 %0, %1, %2, %3;" : "=l"(d) : "l"(a), "l"(b), "l"(c));
    return d;
}
__device__ __forceinline__ float2 up2(u64 v) {
    float2 f; asm("mov.b64 {%0,%1}, %2;" : "=f"(f.x), "=f"(f.y) : "l"(v)); return f;
}

// ---- warp-level bf16 MMA (sm_80+ path; works on plain sm_103 target) ----
__device__ __forceinline__ void mma_bf16(float* c, u32 a0, u32 a1, u32 a2, u32 a3,
                                         u32 b0, u32 b1) {
    asm volatile(
        "mma.sync.aligned.m16n8k16.row.col.f32.bf16.bf16.f32 "
        "{%0,%1,%2,%3}, {%4,%5,%6,%7}, {%8,%9}, {%0,%1,%2,%3};"
        : "+f"(c[0]), "+f"(c[1]), "+f"(c[2]), "+f"(c[3])
        : "r"(a0), "r"(a1), "r"(a2), "r"(a3), "r"(b0), "r"(b1));
}
__device__ __forceinline__ u32 smem_u32addr(const void* p) {
    u32 a;
    asm("{ .reg .u64 t; cvta.to.shared.u64 t, %1; cvt.u32.u64 %0, t; }" : "=r"(a) : "l"(p));
    return a;
}
__device__ __forceinline__ void cp_async16(u32 dst, const void* src) {
    asm volatile("cp.async.cg.shared.global [%0], [%1], 16;" :: "r"(dst), "l"(src));
}
#define CP_COMMIT() asm volatile("cp.async.commit_group;" ::: "memory")
#define CP_WAIT0()  asm volatile("cp.async.wait_group 0;" ::: "memory")

// ---------------- device scratch ----------------
__device__ float g_x[BB * TSEQ * DD];
__device__ float g_feats[BB * TSEQ * DD];
__device__ float g_Wt[2 * 3 * 512 * NG];
__device__ float g_cur[2 * 2 * 2 * BB * DD];
__device__ float g_h[2 * 3 * 2 * BB * HH];
__device__ float g_c[2 * 3 * BB * HH];
__device__ unsigned g_sync;
__device__ u32 g_xh2[BB * TSEQ * 128];        // bf16x2 hi plane of x
__device__ u32 g_xl2[BB * TSEQ * 128];        // bf16x2 lo plane of x
__device__ u32 g_Wb2[2 * 15 * 2 * 32768];     // packed W: [iter][tap][plane][n256][k256] bf16

// ---------------- embedding gather ----------------
__global__ void k_embed(const int* __restrict__ tokens, const float* __restrict__ E) {
    int row = blockIdx.x;
    int tok = tokens[row];
    const float4* src = reinterpret_cast<const float4*>(E) + (size_t)tok * (DD / 4);
    float4* dst = reinterpret_cast<float4*>(g_x) + (size_t)row * (DD / 4);
    dst[threadIdx.x] = src[threadIdx.x];
}

// ---------------- W pack: [iter][tap][plane][n][k] bf16 (once) ------------
__global__ void k_wprep(const float* __restrict__ W3, const float* __restrict__ W5,
                        const float* __restrict__ W7) {
    int idx = blockIdx.x * 256 + threadIdx.x;
    const int TOT = 2 * 15 * 2 * 65536;
    if (idx >= TOT) return;
    int k     = idx & 255;
    int n     = (idx >> 8) & 255;
    int plane = (idx >> 16) & 1;
    int tp    = idx >> 17;               // 0..29
    int tap   = tp % 15;
    int iter  = tp / 15;
    const float* Wsrc; int kk, KW;
    if (tap < 3)      { Wsrc = W3; kk = tap;     KW = 3; }
    else if (tap < 8) { Wsrc = W5; kk = tap - 3; KW = 5; }
    else              { Wsrc = W7; kk = tap - 8; KW = 7; }
    float v = Wsrc[(((size_t)iter * KW + kk) * 256 + k) * 256 + n];
    __nv_bfloat16 hi = __float2bfloat16(v);
    __nv_bfloat16 val = plane ? __float2bfloat16(v - __bfloat162float(hi)) : hi;
    __nv_bfloat16* dst = reinterpret_cast<__nv_bfloat16*>(g_Wb2);
    dst[(size_t)(((iter * 15 + tap) * 2 + plane)) * 65536 + n * 256 + k] = val;
}

// ---------------- x split into bf16x2 hi/lo planes (per conv iter) --------
__global__ void k_xsplit() {
    size_t idx = (size_t)blockIdx.x * 256 + threadIdx.x;
    float a0 = g_x[idx * 2], a1 = g_x[idx * 2 + 1];
    __nv_bfloat16 h0 = __float2bfloat16(a0), h1 = __float2bfloat16(a1);
    __nv_bfloat16 l0 = __float2bfloat16(a0 - __bfloat162float(h0));
    __nv_bfloat16 l1 = __float2bfloat16(a1 - __bfloat162float(h1));
    __nv_bfloat162 hp; hp.x = h0; hp.y = h1;
    __nv_bfloat162 lp; lp.x = l0; lp.y = l1;
    g_xh2[idx] = *reinterpret_cast<u32*>(&hp);
    g_xl2[idx] = *reinterpret_cast<u32*>(&lp);
}

// ---------------- conv bank on HMMA (split-bf16) ---------------------------
// Block 256 thr: tile 64t x 64n, K=256, 15 taps as A-row shifts.
// smem(u32): A_hi[70][132] @0, A_lo @9240, B[2 buf][2 plane][64][128 swz] @18480.
// Warp w: m16 tile at (w&3)*16, n32 at (w>>2)*32 (4 n8 tiles).
#define CAP 132
#define SM_AL 9240
#define SM_B  18480
#define SM_CONV_U32 (18480 + 32768)
#define B_CHUNKS 4096   // 2 planes x 64 n x 32 16B-chunks
__global__ void __launch_bounds__(256, 1) k_conv_mma(
    const float* __restrict__ bconv, int iter)
{
    extern __shared__ u32 sm[];
    u32* Ah = sm;
    u32* Al = sm + SM_AL;
    u32* Bb = sm + SM_B;

    const int tid  = threadIdx.x;
    const int warp = tid >> 5, lane = tid & 31;
    const int gid  = lane >> 2, tg = lane & 3;
    const int b    = blockIdx.x >> 3;
    const int t0   = (blockIdx.x & 7) * 64;
    const int n0   = blockIdx.y * 64;
    const int wm   = (warp & 3) * 16;
    const int wn   = (warp >> 2) * 32;

    // ---- stage A window rows t0-3 .. t0+66 (both planes) ----
    for (int idx = tid; idx < 70 * 128; idx += 256) {
        int r = idx >> 7, c = idx & 127;
        int t = t0 - 3 + r;
        u32 vh = 0, vl = 0;
        if (t >= 0 && t < TSEQ) {
            size_t g = ((size_t)b * TSEQ + t) * 128 + c;
            vh = g_xh2[g]; vl = g_xl2[g];
        }
        Ah[r * CAP + c] = vh;
        Al[r * CAP + c] = vl;
    }

    // ---- prefetch B for tap 0 into buf 0 ----
    const size_t wbase = (size_t)(iter * 15) * 2 * 32768;
    {
        for (int i = tid; i < B_CHUNKS; i += 256) {
            int p = i >> 11, rem = i & 2047;
            int n = rem >> 5, cq = rem & 31;
            int c0 = cq * 4;
            u32 dsw = (u32)c0 ^ (((u32)n & 7) << 2);
            u32 dst = smem_u32addr(Bb + p * 8192 + n * 128 + dsw);
            const u32* src = g_Wb2 + wbase + (size_t)p * 32768 + (size_t)(n0 + n) * 128 + c0;
            cp_async16(dst, src);
        }
        CP_COMMIT();
    }
    CP_WAIT0();
    __syncthreads();

    float acc[3][4][4];
#pragma unroll
    for (int w = 0; w < 3; ++w)
#pragma unroll
        for (int j = 0; j < 4; ++j)
#pragma unroll
            for (int q = 0; q < 4; ++q) acc[w][j][q] = 0.f;

    for (int tap = 0; tap < 15; ++tap) {
        int widx, kk;
        if (tap < 3)      { widx = 0; kk = tap; }
        else if (tap < 8) { widx = 1; kk = tap - 3; }
        else              { widx = 2; kk = tap - 8; }
        const int shift = kk - widx - 1;
        const int buf = tap & 1;

        // prefetch next tap's B into the other buffer
        if (tap < 14) {
            const size_t nb = (size_t)((iter * 15 + tap + 1) * 2) * 32768;
            u32* Bo = Bb + (buf ^ 1) * 16384;
            for (int i = tid; i < B_CHUNKS; i += 256) {
                int p = i >> 11, rem = i & 2047;
                int n = rem >> 5, cq = rem & 31;
                int c0 = cq * 4;
                u32 dsw = (u32)c0 ^ (((u32)n & 7) << 2);
                u32 dst = smem_u32addr(Bo + p * 8192 + n * 128 + dsw);
                const u32* src = g_Wb2 + nb + (size_t)p * 32768 + (size_t)(n0 + n) * 128 + c0;
                cp_async16(dst, src);
            }
            CP_COMMIT();
        }

        // compute this tap
        const u32* Bh = Bb + buf * 16384;
        const u32* Bl = Bh + 8192;
        const int r0 = 3 + shift + wm + gid;
        const u32* arh0 = Ah + r0 * CAP;
        const u32* arh1 = arh0 + 8 * CAP;
        const u32* arl0 = Al + r0 * CAP;
        const u32* arl1 = arl0 + 8 * CAP;
        float* accw = &acc[widx][0][0];

#pragma unroll
        for (int ks = 0; ks < 16; ++ks) {
            const int kc2 = ks * 8;
            u32 ah0 = arh0[kc2 + tg],     ah1 = arh1[kc2 + tg];
            u32 ah2 = arh0[kc2 + tg + 4], ah3 = arh1[kc2 + tg + 4];
            u32 al0 = arl0[kc2 + tg],     al1 = arl1[kc2 + tg];
            u32 al2 = arl0[kc2 + tg + 4], al3 = arl1[kc2 + tg + 4];
#pragma unroll
            for (int j8 = 0; j8 < 4; ++j8) {
                int nl = wn + j8 * 8 + gid;
                u32 xr = ((u32)(nl & 7)) << 2;
                const u32* bhp = Bh + nl * 128;
                const u32* blp = Bl + nl * 128;
                u32 bh0 = bhp[(kc2 + tg) ^ xr];
                u32 bh1 = bhp[(kc2 + tg + 4) ^ xr];
                u32 bl0 = blp[(kc2 + tg) ^ xr];
                u32 bl1 = blp[(kc2 + tg + 4) ^ xr];
                float* cc = accw + j8 * 4;
                mma_bf16(cc, ah0, ah1, ah2, ah3, bh0, bh1);   // hi*hi
                mma_bf16(cc, ah0, ah1, ah2, ah3, bl0, bl1);   // hi*lo
                mma_bf16(cc, al0, al1, al2, al3, bh0, bh1);   // lo*hi
            }
        }

        if (tap < 14) {
            CP_WAIT0();
            __syncthreads();
        }
    }

    // ---- epilogue: tanh(c3+b3)+tanh(c5+b5)+tanh(c7+b7)+x ----
    {
        const float* b3 = bconv + (iter * 3 + 0) * 256 + n0;
        const float* b5 = bconv + (iter * 3 + 1) * 256 + n0;
        const float* b7 = bconv + (iter * 3 + 2) * 256 + n0;
        const int trow = t0 + wm + gid;
#pragma unroll
        for (int j8 = 0; j8 < 4; ++j8) {
            int cl = wn + j8 * 8 + tg * 2;    // local col (0..63)
            float bb3a = b3[cl], bb3b = b3[cl + 1];
            float bb5a = b5[cl], bb5b = b5[cl + 1];
            float bb7a = b7[cl], bb7b = b7[cl + 1];
#pragma unroll
            for (int rh = 0; rh < 2; ++rh) {
                size_t row = (size_t)b * TSEQ + trow + rh * 8;
                const float2 xv = *reinterpret_cast<const float2*>(
                    g_x + row * 256 + n0 + cl);
                float c3a = acc[0][j8][rh * 2 + 0], c3b = acc[0][j8][rh * 2 + 1];
                float c5a = acc[1][j8][rh * 2 + 0], c5b = acc[1][j8][rh * 2 + 1];
                float c7a = acc[2][j8][rh * 2 + 0], c7b = acc[2][j8][rh * 2 + 1];
                float2 o;
                o.x = tanhf(c3a + bb3a) + tanhf(c5a + bb5a) + tanhf(c7a + bb7a) + xv.x;
                o.y = tanhf(c3b + bb3b) + tanhf(c5b + bb5b) + tanhf(c7b + bb7b) + xv.y;
                *reinterpret_cast<float2*>(g_feats + row * 256 + n0 + cl) = o;
            }
        }
    }
}

// ---------------- layernorm ----------------
__global__ void k_ln(const float* __restrict__ gamma, const float* __restrict__ beta, int iter) {
    int wid = threadIdx.x >> 5, lane = threadIdx.x & 31;
    int row = blockIdx.x * 8 + wid;
    const float4* f = reinterpret_cast<const float4*>(g_feats + (size_t)row * DD);
    float4 v0 = f[lane];
    float4 v1 = f[32 + lane];
    float s = v0.x + v0.y + v0.z + v0.w + v1.x + v1.y + v1.z + v1.w;
    float q = v0.x*v0.x + v0.y*v0.y + v0.z*v0.z + v0.w*v0.w +
              v1.x*v1.x + v1.y*v1.y + v1.z*v1.z + v1.w*v1.w;
#pragma unroll
    for (int ofs = 16; ofs; ofs >>= 1) {
        s += __shfl_xor_sync(0xffffffffu, s, ofs);
        q += __shfl_xor_sync(0xffffffffu, q, ofs);
    }
    float mean = s * (1.f / 256.f);
    float var  = q * (1.f / 256.f) - mean * mean;
    float rstd = rsqrtf(var + 1e-3f);

    const float* ga = gamma + iter * DD;
    const float* be = beta + iter * DD;
    float4* xo = reinterpret_cast<float4*>(g_x + (size_t)row * DD);
    int c0 = lane * 4;
    float4 r0, r1;
    r0.x = (v0.x - mean) * rstd * ga[c0 + 0] + be[c0 + 0];
    r0.y = (v0.y - mean) * rstd * ga[c0 + 1] + be[c0 + 1];
    r0.z = (v0.z - mean) * rstd * ga[c0 + 2] + be[c0 + 2];
    r0.w = (v0.w - mean) * rstd * ga[c0 + 3] + be[c0 + 3];
    r1.x = (v1.x - mean) * rstd * ga[128 + c0 + 0] + be[128 + c0 + 0];
    r1.y = (v1.y - mean) * rstd * ga[128 + c0 + 1] + be[128 + c0 + 1];
    r1.z = (v1.z - mean) * rstd * ga[128 + c0 + 2] + be[128 + c0 + 2];
    r1.w = (v1.w - mean) * rstd * ga[128 + c0 + 3] + be[128 + c0 + 3];
    xo[lane] = r0;
    xo[32 + lane] = r1;
}

// ---------------- weight pre-transpose: [dl][k][col*4+g] ----------------
__global__ void k_transpose(const float* __restrict__ Wx, const float* __restrict__ Wh) {
    int idx = blockIdx.x * 256 + threadIdx.x;
    if (idx >= 2 * 3 * 512 * NG) return;
    int dl  = idx / (512 * NG);
    int rem = idx % (512 * NG);
    int k   = rem / NG;
    int cp  = rem % NG;
    int col = cp >> 2, g = cp & 3;
    int n = g * 256 + col;
    float v = (k < 256) ? Wx[(size_t)dl * 256 * NG + (size_t)k * NG + n]
                        : Wh[(size_t)dl * 256 * NG + (size_t)(k - 256) * NG + n];
    g_Wt[idx] = v;
}

__global__ void k_zero() {
    int i = blockIdx.x * 256 + threadIdx.x;
    if (i < 2 * 3 * 2 * BB * HH) g_h[i] = 0.f;
    if (i < 2 * 3 * BB * HH)     g_c[i] = 0.f;
    if (i == 0) g_sync = 0u;
}

// ---------------- persistent wavefront LSTM (EXACT R6 — best known) -------
__global__ void __launch_bounds__(256, 1) k_lstm_persist(
    const float* __restrict__ blstm, float* __restrict__ out)
{
    extern __shared__ float smem[];
    float* sWr = smem;
    float* sA  = smem + 512 * 64;

    const int bx    = blockIdx.x;
    const int ls    = bx >> 4;
    const int dir   = ls & 1;
    const int layer = ls >> 1;
    const int sub   = bx & 15;
    const int j0    = sub * 16;
    const int tid   = threadIdx.x;
    const int jc    = tid & 15;
    const int mq    = tid >> 4;
    const int dl    = dir * 3 + layer;

    {
        const float4* src = reinterpret_cast<const float4*>(
            g_Wt + (size_t)dl * 512 * NG);
        float4* dst = reinterpret_cast<float4*>(sWr);
        for (int i = tid; i < 512 * 16; i += 256) {
            int k = i >> 4, q = i & 15;
            dst[k * 16 + q] = src[(size_t)k * 256 + j0 + q];
        }
    }

    const int col = j0 + jc;
    const float* bbias = blstm + (size_t)dl * NG;
    const float bi  = bbias[col];
    const float bf_ = bbias[256 + col];
    const float bg  = bbias[512 + col];
    const float bo  = bbias[768 + col];
    float* cbuf = g_c + (size_t)dl * BB * HH;

    const int ftm = tid >> 1;
    const int ffk = (tid & 1) * 16;

    const unsigned nb = gridDim.x;
    const int lprev = (layer > 0) ? (layer - 1) : 0;

    for (int w = 0; w < TSEQ + 2; ++w) {
        const int t = w - layer;
        if (t >= 0 && t < TSEQ) {
            const int tt = dir ? (TSEQ - 1 - t) : t;
            const int rp = t & 1, wp = rp ^ 1;
            const float* hin = g_h + (size_t)(dl * 2 + rp) * BB * HH;
            const float* cursrc = g_cur +
                (size_t)((dir * 2 + lprev) * 2 + (t & 1)) * BB * DD;
            float* curdst = g_cur +
                (size_t)((dir * 2 + layer) * 2 + (t & 1)) * BB * DD;

            u64 acc[4][4];
            const u64 zz = pk2(0.f, 0.f);
#pragma unroll
            for (int g = 0; g < 4; ++g)
#pragma unroll
                for (int p = 0; p < 4; ++p) acc[g][p] = zz;

            float4 va[4];
            {
                const float* src = (layer == 0)
                    ? (g_x + ((size_t)ftm * TSEQ + tt) * DD + ffk)
                    : (cursrc + (size_t)ftm * DD + ffk);
#pragma unroll
                for (int i = 0; i < 4; ++i)
                    va[i] = *reinterpret_cast<const float4*>(src + i * 4);
            }
            {
                float* dstbuf = sA;
#pragma unroll
                for (int i = 0; i < 4; ++i) {
                    dstbuf[(ffk + i * 4 + 0) * APITCH + ftm] = va[i].x;
                    dstbuf[(ffk + i * 4 + 1) * APITCH + ftm] = va[i].y;
                    dstbuf[(ffk + i * 4 + 2) * APITCH + ftm] = va[i].z;
                    dstbuf[(ffk + i * 4 + 3) * APITCH + ftm] = va[i].w;
                }
            }
            __syncthreads();

            for (int ci = 0; ci < 16; ++ci) {
                if (ci < 15) {
                    int kk = (ci + 1) * 32 + ffk;
                    if (kk < 256) {
                        const float* src = (layer == 0)
                            ? (g_x + ((size_t)ftm * TSEQ + tt) * DD + kk)
                            : (cursrc + (size_t)ftm * DD + kk);
                        va[0] = *reinterpret_cast<const float4*>(src);
                        va[1] = *reinterpret_cast<const float4*>(src + 4);
                        va[2] = *reinterpret_cast<const float4*>(src + 8);
                        va[3] = *reinterpret_cast<const float4*>(src + 12);
                    } else {
                        const float4* src = reinterpret_cast<const float4*>(
                            hin + (size_t)ftm * HH + (kk - 256));
                        va[0] = __ldcg(src);
                        va[1] = __ldcg(src + 1);
                        va[2] = __ldcg(src + 2);
                        va[3] = __ldcg(src + 3);
                    }
                }

                const float* ab = sA + (ci & 1) * (32 * APITCH);
                const float* wb = sWr + (size_t)ci * 32 * 64 + jc * 4;
#pragma unroll
                for (int k = 0; k < 32; ++k) {
                    const float* ar = ab + k * APITCH + mq * 8;
                    u64 a0 = *reinterpret_cast<const u64*>(ar + 0);
                    u64 a1 = *reinterpret_cast<const u64*>(ar + 2);
                    u64 a2 = *reinterpret_cast<const u64*>(ar + 4);
                    u64 a3 = *reinterpret_cast<const u64*>(ar + 6);
                    float4 wv = *reinterpret_cast<const float4*>(wb + k * 64);
                    u64 w0 = pk2(wv.x, wv.x);
                    u64 w1 = pk2(wv.y, wv.y);
                    u64 w2 = pk2(wv.z, wv.z);
                    u64 w3 = pk2(wv.w, wv.w);
                    acc[0][0] = ff2(a0, w0, acc[0][0]); acc[0][1] = ff2(a1, w0, acc[0][1]);
                    acc[0][2] = ff2(a2, w0, acc[0][2]); acc[0][3] = ff2(a3, w0, acc[0][3]);
                    acc[1][0] = ff2(a0, w1, acc[1][0]); acc[1][1] = ff2(a1, w1, acc[1][1]);
                    acc[1][2] = ff2(a2, w1, acc[1][2]); acc[1][3] = ff2(a3, w1, acc[1][3]);
                    acc[2][0] = ff2(a0, w2, acc[2][0]); acc[2][1] = ff2(a1, w2, acc[2][1]);
                    acc[2][2] = ff2(a2, w2, acc[2][2]); acc[2][3] = ff2(a3, w2, acc[2][3]);
                    acc[3][0] = ff2(a0, w3, acc[3][0]); acc[3][1] = ff2(a1, w3, acc[3][1]);
                    acc[3][2] = ff2(a2, w3, acc[3][2]); acc[3][3] = ff2(a3, w3, acc[3][3]);
                }

                if (ci < 15) {
                    float* dstbuf = sA + ((ci + 1) & 1) * (32 * APITCH);
#pragma unroll
                    for (int i = 0; i < 4; ++i) {
                        dstbuf[(ffk + i * 4 + 0) * APITCH + ftm] = va[i].x;
                        dstbuf[(ffk + i * 4 + 1) * APITCH + ftm] = va[i].y;
                        dstbuf[(ffk + i * 4 + 2) * APITCH + ftm] = va[i].z;
                        dstbuf[(ffk + i * 4 + 3) * APITCH + ftm] = va[i].w;
                    }
                    __syncthreads();
                }
            }

            float* hout = g_h + (size_t)(dl * 2 + wp) * BB * HH;
#pragma unroll
            for (int p = 0; p < 4; ++p) {
                float2 zi = up2(acc[0][p]);
                float2 zf = up2(acc[1][p]);
                float2 zg = up2(acc[2][p]);
                float2 zo = up2(acc[3][p]);
#pragma unroll
                for (int h2 = 0; h2 < 2; ++h2) {
                    int m = mq * 8 + p * 2 + h2;
                    float vzi = (h2 ? zi.y : zi.x) + bi;
                    float vzf = (h2 ? zf.y : zf.x) + bf_;
                    float vzg = (h2 ? zg.y : zg.x) + bg;
                    float vzo = (h2 ? zo.y : zo.x) + bo;
                    float ig = 1.f / (1.f + expf(-vzi));
                    float fg = 1.f / (1.f + expf(-vzf));
                    float gg = tanhf(vzg);
                    float og = 1.f / (1.f + expf(-vzo));
                    float cp = cbuf[(size_t)m * HH + col];
                    float cn = fg * cp + ig * gg;
                    float hn = og * tanhf(cn);
                    cbuf[(size_t)m * HH + col] = cn;
                    hout[(size_t)m * HH + col] = hn;
                    float ain = (layer == 0)
                        ? g_x[((size_t)m * TSEQ + tt) * DD + col]
                        : __ldcg(cursrc + (size_t)m * DD + col);
                    float cu = ain + hn;
                    if (layer == 2)
                        out[((size_t)m * TSEQ + tt) * 512 + dir * 256 + col] = cu;
                    else
                        curdst[(size_t)m * DD + col] = cu;
                }
            }
        }

        __syncthreads();
        __threadfence();
        if (tid == 0) {
            atomicAdd(&g_sync, 1u);
            unsigned target = nb * (unsigned)(w + 1);
            while (*(volatile unsigned*)&g_sync < target) __nanosleep(64);
        }
        __syncthreads();
    }
}

// ---------------- final states ----------------
__global__ void k_states(float* __restrict__ out) {
    int idx = blockIdx.x * 256 + threadIdx.x;
    if (idx >= 2 * 3 * BB * HH) return;
    int j  = idx & 255;
    int m  = (idx >> 8) & 127;
    int dl = idx >> 15;
    const size_t SEQ = (size_t)BB * TSEQ * 512;
    const size_t SH  = 2 * 3 * BB * HH;
    out[SEQ + idx]      = g_h[(size_t)(dl * 2 + 0) * BB * HH + (size_t)m * HH + j];
    out[SEQ + SH + idx] = g_c[(size_t)dl * BB * HH + (size_t)m * HH + j];
}

// ---------------- launch ----------------
extern "C" void kernel_launch(void* const* d_in, const int* in_sizes, int n_in,
                              void* d_out, int out_size) {
    const int*   tokens = (const int*)d_in[0];
    const float* E      = (const float*)d_in[1];
    const float* W3     = (const float*)d_in[2];
    const float* W5     = (const float*)d_in[3];
    const float* W7     = (const float*)d_in[4];
    const float* bconv  = (const float*)d_in[5];
    const float* gamma  = (const float*)d_in[6];
    const float* beta   = (const float*)d_in[7];
    const float* Wx     = (const float*)d_in[8];
    const float* Wh     = (const float*)d_in[9];
    const float* blstm  = (const float*)d_in[10];
    float* out = (float*)d_out;

    const int SMEM_LSTM = (512 * 64 + 2 * 32 * APITCH) * 4;
    const int SMEM_CONV = SM_CONV_U32 * 4;                 // 204,992 B
    static int s_attr = 0;
    if (!s_attr) {
        cudaFuncSetAttribute(k_lstm_persist,
                             cudaFuncAttributeMaxDynamicSharedMemorySize, SMEM_LSTM);
        cudaFuncSetAttribute(k_conv_mma,
                             cudaFuncAttributeMaxDynamicSharedMemorySize, SMEM_CONV);
        s_attr = 1;
    }

    k_embed<<<BB * TSEQ, 64>>>(tokens, E);
    k_wprep<<<(2 * 15 * 2 * 65536 + 255) / 256, 256>>>(W3, W5, W7);
    for (int it = 0; it < 2; ++it) {
        k_xsplit<<<(BB * TSEQ * 128) / 256, 256>>>();
        k_conv_mma<<<dim3(BB * 8, 4), 256, SMEM_CONV>>>(bconv, it);
        k_ln<<<BB * TSEQ / 8, 256>>>(gamma, beta, it);
    }
    k_transpose<<<(2 * 3 * 512 * NG + 255) / 256, 256>>>(Wx, Wh);
    k_zero<<<1536, 256>>>();
    k_lstm_persist<<<NBLK, 256, SMEM_LSTM>>>(blstm, out);
    k_states<<<768, 256>>>(out);
}

// round 12
// speedup vs baseline: 1.9973x; 1.2727x over previous
#include <cuda_runtime.h>
#include <cuda_bf16.h>
#include <math.h>
#include <cstdint>

#define BB   128
#define TSEQ 512
#define DD   256
#define HH   256
#define NG   1024
#define NBLK 96

typedef unsigned long long u64;
typedef unsigned int u32;

// ---- warp-level bf16 MMA (verified in R11) ----
__device__ __forceinline__ void mma_bf16(float* c, u32 a0, u32 a1, u32 a2, u32 a3,
                                         u32 b0, u32 b1) {
    asm volatile(
        "mma.sync.aligned.m16n8k16.row.col.f32.bf16.bf16.f32 "
        "{%0,%1,%2,%3}, {%4,%5,%6,%7}, {%8,%9}, {%0,%1,%2,%3};"
        : "+f"(c[0]), "+f"(c[1]), "+f"(c[2]), "+f"(c[3])
        : "r"(a0), "r"(a1), "r"(a2), "r"(a3), "r"(b0), "r"(b1));
}
__device__ __forceinline__ u32 smem_u32addr(const void* p) {
    u32 a;
    asm("{ .reg .u64 t; cvta.to.shared.u64 t, %1; cvt.u32.u64 %0, t; }" : "=r"(a) : "l"(p));
    return a;
}
__device__ __forceinline__ void cp_async16(u32 dst, const void* src) {
    asm volatile("cp.async.cg.shared.global [%0], [%1], 16;" :: "r"(dst), "l"(src));
}
#define CP_COMMIT() asm volatile("cp.async.commit_group;" ::: "memory")
#define CP_WAIT0()  asm volatile("cp.async.wait_group 0;" ::: "memory")

// ---------------- device scratch ----------------
__device__ float g_x[BB * TSEQ * DD];
__device__ float g_feats[BB * TSEQ * DD];
__device__ float g_cur[2 * 2 * 2 * BB * DD];
__device__ float g_h[2 * 3 * 2 * BB * HH];
__device__ float g_c[2 * 3 * BB * HH];
__device__ unsigned g_sync;
__device__ u32 g_xh2[BB * TSEQ * 128];        // bf16x2 hi plane of x (== bf16 [row][256])
__device__ u32 g_xl2[BB * TSEQ * 128];        // bf16x2 lo plane
__device__ u32 g_Wb2[2 * 15 * 2 * 32768];     // conv W: [iter][tap][plane][n256][k256] bf16
// LSTM bf16 planes
__device__ __nv_bfloat16 g_Wlb[2ull * 6 * 1024 * 512];    // [plane][dl][n=col*4+g][k]
__device__ __nv_bfloat16 g_hbh[6 * 2 * BB * 256];         // h hi  [dl][pp][m][256]
__device__ __nv_bfloat16 g_hbl[6 * 2 * BB * 256];         // h lo
__device__ __nv_bfloat16 g_cbh[2 * 2 * 2 * BB * 256];     // cur hi [dir][stage][par][m][256]
__device__ __nv_bfloat16 g_cbl[2 * 2 * 2 * BB * 256];     // cur lo

// ---------------- embedding gather ----------------
__global__ void k_embed(const int* __restrict__ tokens, const float* __restrict__ E) {
    int row = blockIdx.x;
    int tok = tokens[row];
    const float4* src = reinterpret_cast<const float4*>(E) + (size_t)tok * (DD / 4);
    float4* dst = reinterpret_cast<float4*>(g_x) + (size_t)row * (DD / 4);
    dst[threadIdx.x] = src[threadIdx.x];
}

// ---------------- conv W pack (unchanged, R11-verified) ----------------
__global__ void k_wprep(const float* __restrict__ W3, const float* __restrict__ W5,
                        const float* __restrict__ W7) {
    int idx = blockIdx.x * 256 + threadIdx.x;
    const int TOT = 2 * 15 * 2 * 65536;
    if (idx >= TOT) return;
    int k     = idx & 255;
    int n     = (idx >> 8) & 255;
    int plane = (idx >> 16) & 1;
    int tp    = idx >> 17;
    int tap   = tp % 15;
    int iter  = tp / 15;
    const float* Wsrc; int kk, KW;
    if (tap < 3)      { Wsrc = W3; kk = tap;     KW = 3; }
    else if (tap < 8) { Wsrc = W5; kk = tap - 3; KW = 5; }
    else              { Wsrc = W7; kk = tap - 8; KW = 7; }
    float v = Wsrc[(((size_t)iter * KW + kk) * 256 + k) * 256 + n];
    __nv_bfloat16 hi = __float2bfloat16(v);
    __nv_bfloat16 val = plane ? __float2bfloat16(v - __bfloat162float(hi)) : hi;
    __nv_bfloat16* dst = reinterpret_cast<__nv_bfloat16*>(g_Wb2);
    dst[(size_t)(((iter * 15 + tap) * 2 + plane)) * 65536 + n * 256 + k] = val;
}

// ---------------- LSTM W pack: split bf16 [plane][dl][col*4+g][k] ----------
__global__ void k_wprep_lstm(const float* __restrict__ Wx, const float* __restrict__ Wh) {
    size_t idx = (size_t)blockIdx.x * 256 + threadIdx.x;
    const size_t TOT = 2ull * 6 * 1024 * 512;
    if (idx >= TOT) return;
    int k     = (int)(idx & 511);
    int n     = (int)((idx >> 9) & 1023);     // col*4+g
    int dl    = (int)((idx >> 19) % 6);
    int plane = (int)(idx / (6ull << 19));
    int col = n >> 2, g = n & 3;
    int nc = g * 256 + col;
    float v = (k < 256) ? Wx[(size_t)dl * 256 * NG + (size_t)k * NG + nc]
                        : Wh[(size_t)dl * 256 * NG + (size_t)(k - 256) * NG + nc];
    __nv_bfloat16 hi = __float2bfloat16(v);
    __nv_bfloat16 val = plane ? __float2bfloat16(v - __bfloat162float(hi)) : hi;
    g_Wlb[idx] = val;
}

// ---------------- x split into bf16 hi/lo planes ----------
__global__ void k_xsplit() {
    size_t idx = (size_t)blockIdx.x * 256 + threadIdx.x;
    float a0 = g_x[idx * 2], a1 = g_x[idx * 2 + 1];
    __nv_bfloat16 h0 = __float2bfloat16(a0), h1 = __float2bfloat16(a1);
    __nv_bfloat16 l0 = __float2bfloat16(a0 - __bfloat162float(h0));
    __nv_bfloat16 l1 = __float2bfloat16(a1 - __bfloat162float(h1));
    __nv_bfloat162 hp; hp.x = h0; hp.y = h1;
    __nv_bfloat162 lp; lp.x = l0; lp.y = l1;
    g_xh2[idx] = *reinterpret_cast<u32*>(&hp);
    g_xl2[idx] = *reinterpret_cast<u32*>(&lp);
}

// ---------------- conv bank on HMMA (unchanged from R11, passing) ----------
#define CAP 132
#define SM_AL 9240
#define SM_B  18480
#define SM_CONV_U32 (18480 + 32768)
#define B_CHUNKS 4096
__global__ void __launch_bounds__(256, 1) k_conv_mma(
    const float* __restrict__ bconv, int iter)
{
    extern __shared__ u32 sm[];
    u32* Ah = sm;
    u32* Al = sm + SM_AL;
    u32* Bb = sm + SM_B;

    const int tid  = threadIdx.x;
    const int warp = tid >> 5, lane = tid & 31;
    const int gid  = lane >> 2, tg = lane & 3;
    const int b    = blockIdx.x >> 3;
    const int t0   = (blockIdx.x & 7) * 64;
    const int n0   = blockIdx.y * 64;
    const int wm   = (warp & 3) * 16;
    const int wn   = (warp >> 2) * 32;

    for (int idx = tid; idx < 70 * 128; idx += 256) {
        int r = idx >> 7, c = idx & 127;
        int t = t0 - 3 + r;
        u32 vh = 0, vl = 0;
        if (t >= 0 && t < TSEQ) {
            size_t g = ((size_t)b * TSEQ + t) * 128 + c;
            vh = g_xh2[g]; vl = g_xl2[g];
        }
        Ah[r * CAP + c] = vh;
        Al[r * CAP + c] = vl;
    }

    const size_t wbase = (size_t)(iter * 15) * 2 * 32768;
    {
        for (int i = tid; i < B_CHUNKS; i += 256) {
            int p = i >> 11, rem = i & 2047;
            int n = rem >> 5, cq = rem & 31;
            int c0 = cq * 4;
            u32 dsw = (u32)c0 ^ (((u32)n & 7) << 2);
            u32 dst = smem_u32addr(Bb + p * 8192 + n * 128 + dsw);
            const u32* src = g_Wb2 + wbase + (size_t)p * 32768 + (size_t)(n0 + n) * 128 + c0;
            cp_async16(dst, src);
        }
        CP_COMMIT();
    }
    CP_WAIT0();
    __syncthreads();

    float acc[3][4][4];
#pragma unroll
    for (int w = 0; w < 3; ++w)
#pragma unroll
        for (int j = 0; j < 4; ++j)
#pragma unroll
            for (int q = 0; q < 4; ++q) acc[w][j][q] = 0.f;

    for (int tap = 0; tap < 15; ++tap) {
        int widx, kk;
        if (tap < 3)      { widx = 0; kk = tap; }
        else if (tap < 8) { widx = 1; kk = tap - 3; }
        else              { widx = 2; kk = tap - 8; }
        const int shift = kk - widx - 1;
        const int buf = tap & 1;

        if (tap < 14) {
            const size_t nb = (size_t)((iter * 15 + tap + 1) * 2) * 32768;
            u32* Bo = Bb + (buf ^ 1) * 16384;
            for (int i = tid; i < B_CHUNKS; i += 256) {
                int p = i >> 11, rem = i & 2047;
                int n = rem >> 5, cq = rem & 31;
                int c0 = cq * 4;
                u32 dsw = (u32)c0 ^ (((u32)n & 7) << 2);
                u32 dst = smem_u32addr(Bo + p * 8192 + n * 128 + dsw);
                const u32* src = g_Wb2 + nb + (size_t)p * 32768 + (size_t)(n0 + n) * 128 + c0;
                cp_async16(dst, src);
            }
            CP_COMMIT();
        }

        const u32* Bh = Bb + buf * 16384;
        const u32* Bl = Bh + 8192;
        const int r0 = 3 + shift + wm + gid;
        const u32* arh0 = Ah + r0 * CAP;
        const u32* arh1 = arh0 + 8 * CAP;
        const u32* arl0 = Al + r0 * CAP;
        const u32* arl1 = arl0 + 8 * CAP;
        float* accw = &acc[widx][0][0];

#pragma unroll
        for (int ks = 0; ks < 16; ++ks) {
            const int kc2 = ks * 8;
            u32 ah0 = arh0[kc2 + tg],     ah1 = arh1[kc2 + tg];
            u32 ah2 = arh0[kc2 + tg + 4], ah3 = arh1[kc2 + tg + 4];
            u32 al0 = arl0[kc2 + tg],     al1 = arl1[kc2 + tg];
            u32 al2 = arl0[kc2 + tg + 4], al3 = arl1[kc2 + tg + 4];
#pragma unroll
            for (int j8 = 0; j8 < 4; ++j8) {
                int nl = wn + j8 * 8 + gid;
                u32 xr = ((u32)(nl & 7)) << 2;
                const u32* bhp = Bh + nl * 128;
                const u32* blp = Bl + nl * 128;
                u32 bh0 = bhp[(kc2 + tg) ^ xr];
                u32 bh1 = bhp[(kc2 + tg + 4) ^ xr];
                u32 bl0 = blp[(kc2 + tg) ^ xr];
                u32 bl1 = blp[(kc2 + tg + 4) ^ xr];
                float* cc = accw + j8 * 4;
                mma_bf16(cc, ah0, ah1, ah2, ah3, bh0, bh1);
                mma_bf16(cc, ah0, ah1, ah2, ah3, bl0, bl1);
                mma_bf16(cc, al0, al1, al2, al3, bh0, bh1);
            }
        }

        if (tap < 14) {
            CP_WAIT0();
            __syncthreads();
        }
    }

    {
        const float* b3 = bconv + (iter * 3 + 0) * 256 + n0;
        const float* b5 = bconv + (iter * 3 + 1) * 256 + n0;
        const float* b7 = bconv + (iter * 3 + 2) * 256 + n0;
        const int trow = t0 + wm + gid;
#pragma unroll
        for (int j8 = 0; j8 < 4; ++j8) {
            int cl = wn + j8 * 8 + tg * 2;
            float bb3a = b3[cl], bb3b = b3[cl + 1];
            float bb5a = b5[cl], bb5b = b5[cl + 1];
            float bb7a = b7[cl], bb7b = b7[cl + 1];
#pragma unroll
            for (int rh = 0; rh < 2; ++rh) {
                size_t row = (size_t)b * TSEQ + trow + rh * 8;
                const float2 xv = *reinterpret_cast<const float2*>(
                    g_x + row * 256 + n0 + cl);
                float c3a = acc[0][j8][rh * 2 + 0], c3b = acc[0][j8][rh * 2 + 1];
                float c5a = acc[1][j8][rh * 2 + 0], c5b = acc[1][j8][rh * 2 + 1];
                float c7a = acc[2][j8][rh * 2 + 0], c7b = acc[2][j8][rh * 2 + 1];
                float2 o;
                o.x = tanhf(c3a + bb3a) + tanhf(c5a + bb5a) + tanhf(c7a + bb7a) + xv.x;
                o.y = tanhf(c3b + bb3b) + tanhf(c5b + bb5b) + tanhf(c7b + bb7b) + xv.y;
                *reinterpret_cast<float2*>(g_feats + row * 256 + n0 + cl) = o;
            }
        }
    }
}

// ---------------- layernorm ----------------
__global__ void k_ln(const float* __restrict__ gamma, const float* __restrict__ beta, int iter) {
    int wid = threadIdx.x >> 5, lane = threadIdx.x & 31;
    int row = blockIdx.x * 8 + wid;
    const float4* f = reinterpret_cast<const float4*>(g_feats + (size_t)row * DD);
    float4 v0 = f[lane];
    float4 v1 = f[32 + lane];
    float s = v0.x + v0.y + v0.z + v0.w + v1.x + v1.y + v1.z + v1.w;
    float q = v0.x*v0.x + v0.y*v0.y + v0.z*v0.z + v0.w*v0.w +
              v1.x*v1.x + v1.y*v1.y + v1.z*v1.z + v1.w*v1.w;
#pragma unroll
    for (int ofs = 16; ofs; ofs >>= 1) {
        s += __shfl_xor_sync(0xffffffffu, s, ofs);
        q += __shfl_xor_sync(0xffffffffu, q, ofs);
    }
    float mean = s * (1.f / 256.f);
    float var  = q * (1.f / 256.f) - mean * mean;
    float rstd = rsqrtf(var + 1e-3f);

    const float* ga = gamma + iter * DD;
    const float* be = beta + iter * DD;
    float4* xo = reinterpret_cast<float4*>(g_x + (size_t)row * DD);
    int c0 = lane * 4;
    float4 r0, r1;
    r0.x = (v0.x - mean) * rstd * ga[c0 + 0] + be[c0 + 0];
    r0.y = (v0.y - mean) * rstd * ga[c0 + 1] + be[c0 + 1];
    r0.z = (v0.z - mean) * rstd * ga[c0 + 2] + be[c0 + 2];
    r0.w = (v0.w - mean) * rstd * ga[c0 + 3] + be[c0 + 3];
    r1.x = (v1.x - mean) * rstd * ga[128 + c0 + 0] + be[128 + c0 + 0];
    r1.y = (v1.y - mean) * rstd * ga[128 + c0 + 1] + be[128 + c0 + 1];
    r1.z = (v1.z - mean) * rstd * ga[128 + c0 + 2] + be[128 + c0 + 2];
    r1.w = (v1.w - mean) * rstd * ga[128 + c0 + 3] + be[128 + c0 + 3];
    xo[lane] = r0;
    xo[32 + lane] = r1;
}

__global__ void k_zero() {
    int i = blockIdx.x * 256 + threadIdx.x;   // 393216 threads
    if (i < 196608) {                          // zero h bf16 planes (as u32)
        reinterpret_cast<u32*>(g_hbh)[i] = 0u;
        reinterpret_cast<u32*>(g_hbl)[i] = 0u;
    }
    if (i == 0) g_sync = 0u;
}

// ---------------- persistent wavefront LSTM on HMMA ------------------------
// 96 blocks x 256 thr. Block: 128m x 64n (16 cols x 4 gates), K=512.
// W split-bf16 resident in smem (128KB). A streamed via cp.async dbl-buffer.
#define LAP 36
#define LSTM_SMEM_U32 (32768 + 2 * 2 * 128 * LAP)   // B + A bufs = 51200 u32
__global__ void __launch_bounds__(256, 1) k_lstm_mma(
    const float* __restrict__ blstm, float* __restrict__ out)
{
    extern __shared__ u32 sm[];
    u32* Bs = sm;                 // [plane][64][256] swizzled
    u32* As = sm + 32768;         // [buf][plane][128][LAP]

    const int bx    = blockIdx.x;
    const int ls    = bx >> 4;
    const int dir   = ls & 1;
    const int layer = ls >> 1;
    const int sub   = bx & 15;
    const int j0    = sub * 16;
    const int tid   = threadIdx.x;
    const int warp  = tid >> 5, lane = tid & 31;
    const int gid   = lane >> 2, tg = lane & 3;
    const int wm    = warp * 16;
    const int dl    = dir * 3 + layer;

    // ---- one-time: load W slice (64n x 512k x 2 planes) into smem, swizzled
    for (int i = tid; i < 8192; i += 256) {
        int plane = i >> 12, rem = i & 4095;
        int n = rem >> 6, c0 = (rem & 63) * 4;        // pair chunk base
        u32 dsw = (u32)c0 ^ (((u32)n & 7) << 2);
        u32 dst = smem_u32addr(Bs + plane * 16384 + n * 256 + dsw);
        const __nv_bfloat16* src = g_Wlb +
            ((size_t)(plane * 6 + dl) * 1024 + (j0 * 4 + n)) * 512 + c0 * 2;
        cp_async16(dst, src);
    }
    CP_COMMIT();

    // ---- per-thread constants: bias + c-state regs
    float bias[8][4];
    float creg[8];
#pragma unroll
    for (int j8 = 0; j8 < 8; ++j8) {
        int cg = j0 + 2 * j8 + (tg >> 1);
        bias[j8][0] = blstm[dl * NG + 0 * 256 + cg];
        bias[j8][1] = blstm[dl * NG + 1 * 256 + cg];
        bias[j8][2] = blstm[dl * NG + 2 * 256 + cg];
        bias[j8][3] = blstm[dl * NG + 3 * 256 + cg];
        creg[j8] = 0.f;
    }
    const int ftm = tid >> 1;
    const int fko = (tid & 1) * 32;    // bf16 k offset within 64-k chunk

    CP_WAIT0();
    __syncthreads();

    const unsigned nb = gridDim.x;
    const int lprev = (layer > 0) ? (layer - 1) : 0;
    const __nv_bfloat16* gxh = reinterpret_cast<const __nv_bfloat16*>(g_xh2);
    const __nv_bfloat16* gxl = reinterpret_cast<const __nv_bfloat16*>(g_xl2);

    for (int w = 0; w < TSEQ + 2; ++w) {
        const int t = w - layer;
        if (t >= 0 && t < TSEQ) {
            const int tt = dir ? (TSEQ - 1 - t) : t;
            const int rp = t & 1, wp = rp ^ 1;
            const int par = t & 1;
            const size_t curoffR = (size_t)((dir * 2 + lprev) * 2 + par) * BB * 256;
            const size_t curoffW = (size_t)((dir * 2 + layer) * 2 + par) * BB * 256;
            const size_t hoffR   = (size_t)(dl * 2 + rp) * BB * 256;
            const size_t hoffW   = (size_t)(dl * 2 + wp) * BB * 256;

            // staging source bases for this thread's row ftm
            const __nv_bfloat16 *lowh, *lowl;
            if (layer == 0) {
                lowh = gxh + ((size_t)ftm * TSEQ + tt) * 256;
                lowl = gxl + ((size_t)ftm * TSEQ + tt) * 256;
            } else {
                lowh = g_cbh + curoffR + (size_t)ftm * 256;
                lowl = g_cbl + curoffR + (size_t)ftm * 256;
            }
            const __nv_bfloat16* hh_ = g_hbh + hoffR + (size_t)ftm * 256;
            const __nv_bfloat16* hl_ = g_hbl + hoffR + (size_t)ftm * 256;

            // residual prefetch (my compute rows)
            const int mrow = wm + gid + ((tg & 1) ? 8 : 0);
            float ainv[8];
#pragma unroll
            for (int j8 = 0; j8 < 8; ++j8) {
                int cg = j0 + 2 * j8 + (tg >> 1);
                ainv[j8] = (layer == 0)
                    ? g_x[((size_t)mrow * TSEQ + tt) * 256 + cg]
                    : __ldcg(g_cur + (size_t)((dir * 2 + lprev) * 2 + par) * BB * DD
                             + (size_t)mrow * DD + cg);
            }

            float acc[8][4];
#pragma unroll
            for (int j8 = 0; j8 < 8; ++j8)
#pragma unroll
                for (int q = 0; q < 4; ++q) acc[j8][q] = 0.f;

#define STAGE(ci_, buf_) do {                                              \
    int kb_ = (ci_) * 64 + fko;                                            \
    const __nv_bfloat16 *sh_, *sl_;                                        \
    if (kb_ < 256) { sh_ = lowh + kb_; sl_ = lowl + kb_; }                 \
    else           { sh_ = hh_ + (kb_ - 256); sl_ = hl_ + (kb_ - 256); }   \
    u32 db_ = (buf_) * (2 * 128 * LAP) + ftm * LAP + (fko >> 1);           \
    _Pragma("unroll")                                                      \
    for (int j_ = 0; j_ < 4; ++j_)                                         \
        cp_async16(smem_u32addr(As + db_ + j_ * 4), sh_ + j_ * 8);         \
    db_ += 128 * LAP;                                                      \
    _Pragma("unroll")                                                      \
    for (int j_ = 0; j_ < 4; ++j_)                                         \
        cp_async16(smem_u32addr(As + db_ + j_ * 4), sl_ + j_ * 8);         \
} while (0)

            STAGE(0, 0); CP_COMMIT(); CP_WAIT0(); __syncthreads();

            for (int ci = 0; ci < 8; ++ci) {
                if (ci < 7) { STAGE(ci + 1, (ci + 1) & 1); CP_COMMIT(); }

                const u32* AhB = As + (ci & 1) * (2 * 128 * LAP);
                const u32* AlB = AhB + 128 * LAP;
                const int ra = (wm + gid) * LAP;
                const int rb = (wm + gid + 8) * LAP;
#pragma unroll
                for (int ks = 0; ks < 4; ++ks) {
                    const int pk = ks * 8 + tg;
                    u32 ah0 = AhB[ra + pk],     ah1 = AhB[rb + pk];
                    u32 ah2 = AhB[ra + pk + 4], ah3 = AhB[rb + pk + 4];
                    u32 al0 = AlB[ra + pk],     al1 = AlB[rb + pk];
                    u32 al2 = AlB[ra + pk + 4], al3 = AlB[rb + pk + 4];
                    const int kp = ci * 32 + ks * 8 + tg;
#pragma unroll
                    for (int j8 = 0; j8 < 8; ++j8) {
                        int nl = j8 * 8 + gid;
                        u32 xr = (u32)gid << 2;
                        const u32* bh = Bs + nl * 256;
                        const u32* bl = bh + 16384;
                        u32 b0h = bh[kp ^ xr], b1h = bh[(kp + 4) ^ xr];
                        u32 b0l = bl[kp ^ xr], b1l = bl[(kp + 4) ^ xr];
                        mma_bf16(acc[j8], ah0, ah1, ah2, ah3, b0h, b1h);
                        mma_bf16(acc[j8], ah0, ah1, ah2, ah3, b0l, b1l);
                        mma_bf16(acc[j8], al0, al1, al2, al3, b0h, b1h);
                    }
                }
                if (ci < 7) { CP_WAIT0(); __syncthreads(); }
            }
#undef STAGE

            // ---- epilogue: reunite gates via shfl, cell update, stores ----
            float* curW = g_cur + (size_t)((dir * 2 + layer) * 2 + par) * BB * DD;
#pragma unroll
            for (int j8 = 0; j8 < 8; ++j8) {
                float c0 = acc[j8][0], c1 = acc[j8][1];
                float c2 = acc[j8][2], c3 = acc[j8][3];
                float sendA = (tg & 1) ? c0 : c2;
                float sendB = (tg & 1) ? c1 : c3;
                float rA = __shfl_xor_sync(0xffffffffu, sendA, 1);
                float rB = __shfl_xor_sync(0xffffffffu, sendB, 1);
                float zi, zf, zg, zo;
                if (!(tg & 1)) { zi = c0; zf = c1; zg = rA; zo = rB; }
                else           { zi = rA; zf = rB; zg = c2; zo = c3; }
                zi += bias[j8][0]; zf += bias[j8][1];
                zg += bias[j8][2]; zo += bias[j8][3];
                float ig = 1.f / (1.f + expf(-zi));
                float fg = 1.f / (1.f + expf(-zf));
                float gg = tanhf(zg);
                float og = 1.f / (1.f + expf(-zo));
                float cn = fg * creg[j8] + ig * gg;
                float hn = og * tanhf(cn);
                creg[j8] = cn;
                int cg = j0 + 2 * j8 + (tg >> 1);
                size_t hidx = hoffW + (size_t)mrow * 256 + cg;
                __nv_bfloat16 hh2 = __float2bfloat16(hn);
                g_hbh[hidx] = hh2;
                g_hbl[hidx] = __float2bfloat16(hn - __bfloat162float(hh2));
                g_h[(size_t)(dl * 2 + wp) * BB * HH + (size_t)mrow * HH + cg] = hn;
                if (t == TSEQ - 1)
                    g_c[(size_t)dl * BB * HH + (size_t)mrow * HH + cg] = cn;
                float cu = ainv[j8] + hn;
                if (layer == 2) {
                    out[((size_t)mrow * TSEQ + tt) * 512 + dir * 256 + cg] = cu;
                } else {
                    curW[(size_t)mrow * DD + cg] = cu;
                    size_t cidx = curoffW + (size_t)mrow * 256 + cg;
                    __nv_bfloat16 ch2 = __float2bfloat16(cu);
                    g_cbh[cidx] = ch2;
                    g_cbl[cidx] = __float2bfloat16(cu - __bfloat162float(ch2));
                }
            }
        }

        // ---- grid barrier (proven form) ----
        __syncthreads();
        __threadfence();
        if (tid == 0) {
            atomicAdd(&g_sync, 1u);
            unsigned target = nb * (unsigned)(w + 1);
            while (*(volatile unsigned*)&g_sync < target) __nanosleep(64);
        }
        __syncthreads();
    }
}

// ---------------- final states ----------------
__global__ void k_states(float* __restrict__ out) {
    int idx = blockIdx.x * 256 + threadIdx.x;
    if (idx >= 2 * 3 * BB * HH) return;
    int j  = idx & 255;
    int m  = (idx >> 8) & 127;
    int dl = idx >> 15;
    const size_t SEQ = (size_t)BB * TSEQ * 512;
    const size_t SH  = 2 * 3 * BB * HH;
    out[SEQ + idx]      = g_h[(size_t)(dl * 2 + 0) * BB * HH + (size_t)m * HH + j];
    out[SEQ + SH + idx] = g_c[(size_t)dl * BB * HH + (size_t)m * HH + j];
}

// ---------------- launch ----------------
extern "C" void kernel_launch(void* const* d_in, const int* in_sizes, int n_in,
                              void* d_out, int out_size) {
    const int*   tokens = (const int*)d_in[0];
    const float* E      = (const float*)d_in[1];
    const float* W3     = (const float*)d_in[2];
    const float* W5     = (const float*)d_in[3];
    const float* W7     = (const float*)d_in[4];
    const float* bconv  = (const float*)d_in[5];
    const float* gamma  = (const float*)d_in[6];
    const float* beta   = (const float*)d_in[7];
    const float* Wx     = (const float*)d_in[8];
    const float* Wh     = (const float*)d_in[9];
    const float* blstm  = (const float*)d_in[10];
    float* out = (float*)d_out;

    const int SMEM_CONV = SM_CONV_U32 * 4;
    const int SMEM_LSTM = LSTM_SMEM_U32 * 4;       // 204,800 B
    static int s_attr = 0;
    if (!s_attr) {
        cudaFuncSetAttribute(k_conv_mma,
                             cudaFuncAttributeMaxDynamicSharedMemorySize, SMEM_CONV);
        cudaFuncSetAttribute(k_lstm_mma,
                             cudaFuncAttributeMaxDynamicSharedMemorySize, SMEM_LSTM);
        s_attr = 1;
    }

    k_embed<<<BB * TSEQ, 64>>>(tokens, E);
    k_wprep<<<(2 * 15 * 2 * 65536 + 255) / 256, 256>>>(W3, W5, W7);
    k_wprep_lstm<<<(int)((2ull * 6 * 1024 * 512 + 255) / 256), 256>>>(Wx, Wh);
    for (int it = 0; it < 2; ++it) {
        k_xsplit<<<(BB * TSEQ * 128) / 256, 256>>>();
        k_conv_mma<<<dim3(BB * 8, 4), 256, SMEM_CONV>>>(bconv, it);
        k_ln<<<BB * TSEQ / 8, 256>>>(gamma, beta, it);
    }
    k_xsplit<<<(BB * TSEQ * 128) / 256, 256>>>();   // split post-LN2 x for LSTM
    k_zero<<<1536, 256>>>();
    k_lstm_mma<<<NBLK, 256, SMEM_LSTM>>>(blstm, out);
    k_states<<<768, 256>>>(out);
}

// round 13
// speedup vs baseline: 2.1016x; 1.0522x over previous
#include <cuda_runtime.h>
#include <cuda_bf16.h>
#include <math.h>
#include <cstdint>

#define BB   128
#define TSEQ 512
#define DD   256
#define HH   256
#define NG   1024
#define NBLK 96

typedef unsigned long long u64;
typedef unsigned int u32;

// ---- warp-level bf16 MMA (verified R11/R12) ----
__device__ __forceinline__ void mma_bf16(float* c, u32 a0, u32 a1, u32 a2, u32 a3,
                                         u32 b0, u32 b1) {
    asm volatile(
        "mma.sync.aligned.m16n8k16.row.col.f32.bf16.bf16.f32 "
        "{%0,%1,%2,%3}, {%4,%5,%6,%7}, {%8,%9}, {%0,%1,%2,%3};"
        : "+f"(c[0]), "+f"(c[1]), "+f"(c[2]), "+f"(c[3])
        : "r"(a0), "r"(a1), "r"(a2), "r"(a3), "r"(b0), "r"(b1));
}
__device__ __forceinline__ u32 smem_u32addr(const void* p) {
    u32 a;
    asm("{ .reg .u64 t; cvta.to.shared.u64 t, %1; cvt.u32.u64 %0, t; }" : "=r"(a) : "l"(p));
    return a;
}
__device__ __forceinline__ void cp_async16(u32 dst, const void* src) {
    asm volatile("cp.async.cg.shared.global [%0], [%1], 16;" :: "r"(dst), "l"(src));
}
#define CP_COMMIT() asm volatile("cp.async.commit_group;" ::: "memory")
#define CP_WAIT0()  asm volatile("cp.async.wait_group 0;" ::: "memory")
__device__ __forceinline__ float tanha(float x) {
    float r; asm("tanh.approx.f32 %0, %1;" : "=f"(r) : "f"(x)); return r;
}
__device__ __forceinline__ float sigm(float x) {        // 0.5 + 0.5*tanh(x/2)
    return 0.5f + 0.5f * tanha(0.5f * x);
}

// ---------------- device scratch ----------------
__device__ float g_x[BB * TSEQ * DD];
__device__ float g_feats[BB * TSEQ * DD];
__device__ float g_h[2 * 3 * 2 * BB * HH];
__device__ float g_c[2 * 3 * BB * HH];
__device__ unsigned g_sync;
__device__ u32 g_xh2[BB * TSEQ * 128];        // bf16 hi plane of x ([row][256])
__device__ u32 g_xl2[BB * TSEQ * 128];        // bf16 lo plane
__device__ u32 g_Wb2[2 * 15 * 2 * 32768];     // conv W planes
__device__ __nv_bfloat16 g_Wlb[2ull * 6 * 1024 * 512];    // LSTM W [plane][dl][n][k]
__device__ __nv_bfloat16 g_hbh[6 * 2 * BB * 256];         // h hi
__device__ __nv_bfloat16 g_hbl[6 * 2 * BB * 256];         // h lo
__device__ __nv_bfloat16 g_cbh[2 * 2 * 2 * BB * 256];     // cur hi
__device__ __nv_bfloat16 g_cbl[2 * 2 * 2 * BB * 256];     // cur lo

// ---------------- embedding gather ----------------
__global__ void k_embed(const int* __restrict__ tokens, const float* __restrict__ E) {
    int row = blockIdx.x;
    int tok = tokens[row];
    const float4* src = reinterpret_cast<const float4*>(E) + (size_t)tok * (DD / 4);
    float4* dst = reinterpret_cast<float4*>(g_x) + (size_t)row * (DD / 4);
    dst[threadIdx.x] = src[threadIdx.x];
}

// ---------------- conv W pack (R11-verified) ----------------
__global__ void k_wprep(const float* __restrict__ W3, const float* __restrict__ W5,
                        const float* __restrict__ W7) {
    int idx = blockIdx.x * 256 + threadIdx.x;
    const int TOT = 2 * 15 * 2 * 65536;
    if (idx >= TOT) return;
    int k     = idx & 255;
    int n     = (idx >> 8) & 255;
    int plane = (idx >> 16) & 1;
    int tp    = idx >> 17;
    int tap   = tp % 15;
    int iter  = tp / 15;
    const float* Wsrc; int kk, KW;
    if (tap < 3)      { Wsrc = W3; kk = tap;     KW = 3; }
    else if (tap < 8) { Wsrc = W5; kk = tap - 3; KW = 5; }
    else              { Wsrc = W7; kk = tap - 8; KW = 7; }
    float v = Wsrc[(((size_t)iter * KW + kk) * 256 + k) * 256 + n];
    __nv_bfloat16 hi = __float2bfloat16(v);
    __nv_bfloat16 val = plane ? __float2bfloat16(v - __bfloat162float(hi)) : hi;
    __nv_bfloat16* dst = reinterpret_cast<__nv_bfloat16*>(g_Wb2);
    dst[(size_t)(((iter * 15 + tap) * 2 + plane)) * 65536 + n * 256 + k] = val;
}

// ---------------- LSTM W pack ----------
__global__ void k_wprep_lstm(const float* __restrict__ Wx, const float* __restrict__ Wh) {
    size_t idx = (size_t)blockIdx.x * 256 + threadIdx.x;
    const size_t TOT = 2ull * 6 * 1024 * 512;
    if (idx >= TOT) return;
    int k     = (int)(idx & 511);
    int n     = (int)((idx >> 9) & 1023);
    int dl    = (int)((idx >> 19) % 6);
    int plane = (int)(idx / (6ull << 19));
    int col = n >> 2, g = n & 3;
    int nc = g * 256 + col;
    float v = (k < 256) ? Wx[(size_t)dl * 256 * NG + (size_t)k * NG + nc]
                        : Wh[(size_t)dl * 256 * NG + (size_t)(k - 256) * NG + nc];
    __nv_bfloat16 hi = __float2bfloat16(v);
    __nv_bfloat16 val = plane ? __float2bfloat16(v - __bfloat162float(hi)) : hi;
    g_Wlb[idx] = val;
}

// ---------------- x split ----------
__global__ void k_xsplit() {
    size_t idx = (size_t)blockIdx.x * 256 + threadIdx.x;
    float a0 = g_x[idx * 2], a1 = g_x[idx * 2 + 1];
    __nv_bfloat16 h0 = __float2bfloat16(a0), h1 = __float2bfloat16(a1);
    __nv_bfloat16 l0 = __float2bfloat16(a0 - __bfloat162float(h0));
    __nv_bfloat16 l1 = __float2bfloat16(a1 - __bfloat162float(h1));
    __nv_bfloat162 hp; hp.x = h0; hp.y = h1;
    __nv_bfloat162 lp; lp.x = l0; lp.y = l1;
    g_xh2[idx] = *reinterpret_cast<u32*>(&hp);
    g_xl2[idx] = *reinterpret_cast<u32*>(&lp);
}

// ---------------- conv bank on HMMA (unchanged, passing) ----------
#define CAP 132
#define SM_AL 9240
#define SM_B  18480
#define SM_CONV_U32 (18480 + 32768)
#define B_CHUNKS 4096
__global__ void __launch_bounds__(256, 1) k_conv_mma(
    const float* __restrict__ bconv, int iter)
{
    extern __shared__ u32 sm[];
    u32* Ah = sm;
    u32* Al = sm + SM_AL;
    u32* Bb = sm + SM_B;

    const int tid  = threadIdx.x;
    const int warp = tid >> 5, lane = tid & 31;
    const int gid  = lane >> 2, tg = lane & 3;
    const int b    = blockIdx.x >> 3;
    const int t0   = (blockIdx.x & 7) * 64;
    const int n0   = blockIdx.y * 64;
    const int wm   = (warp & 3) * 16;
    const int wn   = (warp >> 2) * 32;

    for (int idx = tid; idx < 70 * 128; idx += 256) {
        int r = idx >> 7, c = idx & 127;
        int t = t0 - 3 + r;
        u32 vh = 0, vl = 0;
        if (t >= 0 && t < TSEQ) {
            size_t g = ((size_t)b * TSEQ + t) * 128 + c;
            vh = g_xh2[g]; vl = g_xl2[g];
        }
        Ah[r * CAP + c] = vh;
        Al[r * CAP + c] = vl;
    }

    const size_t wbase = (size_t)(iter * 15) * 2 * 32768;
    {
        for (int i = tid; i < B_CHUNKS; i += 256) {
            int p = i >> 11, rem = i & 2047;
            int n = rem >> 5, cq = rem & 31;
            int c0 = cq * 4;
            u32 dsw = (u32)c0 ^ (((u32)n & 7) << 2);
            u32 dst = smem_u32addr(Bb + p * 8192 + n * 128 + dsw);
            const u32* src = g_Wb2 + wbase + (size_t)p * 32768 + (size_t)(n0 + n) * 128 + c0;
            cp_async16(dst, src);
        }
        CP_COMMIT();
    }
    CP_WAIT0();
    __syncthreads();

    float acc[3][4][4];
#pragma unroll
    for (int w = 0; w < 3; ++w)
#pragma unroll
        for (int j = 0; j < 4; ++j)
#pragma unroll
            for (int q = 0; q < 4; ++q) acc[w][j][q] = 0.f;

    for (int tap = 0; tap < 15; ++tap) {
        int widx, kk;
        if (tap < 3)      { widx = 0; kk = tap; }
        else if (tap < 8) { widx = 1; kk = tap - 3; }
        else              { widx = 2; kk = tap - 8; }
        const int shift = kk - widx - 1;
        const int buf = tap & 1;

        if (tap < 14) {
            const size_t nb = (size_t)((iter * 15 + tap + 1) * 2) * 32768;
            u32* Bo = Bb + (buf ^ 1) * 16384;
            for (int i = tid; i < B_CHUNKS; i += 256) {
                int p = i >> 11, rem = i & 2047;
                int n = rem >> 5, cq = rem & 31;
                int c0 = cq * 4;
                u32 dsw = (u32)c0 ^ (((u32)n & 7) << 2);
                u32 dst = smem_u32addr(Bo + p * 8192 + n * 128 + dsw);
                const u32* src = g_Wb2 + nb + (size_t)p * 32768 + (size_t)(n0 + n) * 128 + c0;
                cp_async16(dst, src);
            }
            CP_COMMIT();
        }

        const u32* Bh = Bb + buf * 16384;
        const u32* Bl = Bh + 8192;
        const int r0 = 3 + shift + wm + gid;
        const u32* arh0 = Ah + r0 * CAP;
        const u32* arh1 = arh0 + 8 * CAP;
        const u32* arl0 = Al + r0 * CAP;
        const u32* arl1 = arl0 + 8 * CAP;
        float* accw = &acc[widx][0][0];

#pragma unroll
        for (int ks = 0; ks < 16; ++ks) {
            const int kc2 = ks * 8;
            u32 ah0 = arh0[kc2 + tg],     ah1 = arh1[kc2 + tg];
            u32 ah2 = arh0[kc2 + tg + 4], ah3 = arh1[kc2 + tg + 4];
            u32 al0 = arl0[kc2 + tg],     al1 = arl1[kc2 + tg];
            u32 al2 = arl0[kc2 + tg + 4], al3 = arl1[kc2 + tg + 4];
#pragma unroll
            for (int j8 = 0; j8 < 4; ++j8) {
                int nl = wn + j8 * 8 + gid;
                u32 xr = ((u32)(nl & 7)) << 2;
                const u32* bhp = Bh + nl * 128;
                const u32* blp = Bl + nl * 128;
                u32 bh0 = bhp[(kc2 + tg) ^ xr];
                u32 bh1 = bhp[(kc2 + tg + 4) ^ xr];
                u32 bl0 = blp[(kc2 + tg) ^ xr];
                u32 bl1 = blp[(kc2 + tg + 4) ^ xr];
                float* cc = accw + j8 * 4;
                mma_bf16(cc, ah0, ah1, ah2, ah3, bh0, bh1);
                mma_bf16(cc, ah0, ah1, ah2, ah3, bl0, bl1);
                mma_bf16(cc, al0, al1, al2, al3, bh0, bh1);
            }
        }

        if (tap < 14) {
            CP_WAIT0();
            __syncthreads();
        }
    }

    {
        const float* b3 = bconv + (iter * 3 + 0) * 256 + n0;
        const float* b5 = bconv + (iter * 3 + 1) * 256 + n0;
        const float* b7 = bconv + (iter * 3 + 2) * 256 + n0;
        const int trow = t0 + wm + gid;
#pragma unroll
        for (int j8 = 0; j8 < 4; ++j8) {
            int cl = wn + j8 * 8 + tg * 2;
            float bb3a = b3[cl], bb3b = b3[cl + 1];
            float bb5a = b5[cl], bb5b = b5[cl + 1];
            float bb7a = b7[cl], bb7b = b7[cl + 1];
#pragma unroll
            for (int rh = 0; rh < 2; ++rh) {
                size_t row = (size_t)b * TSEQ + trow + rh * 8;
                const float2 xv = *reinterpret_cast<const float2*>(
                    g_x + row * 256 + n0 + cl);
                float c3a = acc[0][j8][rh * 2 + 0], c3b = acc[0][j8][rh * 2 + 1];
                float c5a = acc[1][j8][rh * 2 + 0], c5b = acc[1][j8][rh * 2 + 1];
                float c7a = acc[2][j8][rh * 2 + 0], c7b = acc[2][j8][rh * 2 + 1];
                float2 o;
                o.x = tanha(c3a + bb3a) + tanha(c5a + bb5a) + tanha(c7a + bb7a) + xv.x;
                o.y = tanha(c3b + bb3b) + tanha(c5b + bb5b) + tanha(c7b + bb7b) + xv.y;
                *reinterpret_cast<float2*>(g_feats + row * 256 + n0 + cl) = o;
            }
        }
    }
}

// ---------------- layernorm ----------------
__global__ void k_ln(const float* __restrict__ gamma, const float* __restrict__ beta, int iter) {
    int wid = threadIdx.x >> 5, lane = threadIdx.x & 31;
    int row = blockIdx.x * 8 + wid;
    const float4* f = reinterpret_cast<const float4*>(g_feats + (size_t)row * DD);
    float4 v0 = f[lane];
    float4 v1 = f[32 + lane];
    float s = v0.x + v0.y + v0.z + v0.w + v1.x + v1.y + v1.z + v1.w;
    float q = v0.x*v0.x + v0.y*v0.y + v0.z*v0.z + v0.w*v0.w +
              v1.x*v1.x + v1.y*v1.y + v1.z*v1.z + v1.w*v1.w;
#pragma unroll
    for (int ofs = 16; ofs; ofs >>= 1) {
        s += __shfl_xor_sync(0xffffffffu, s, ofs);
        q += __shfl_xor_sync(0xffffffffu, q, ofs);
    }
    float mean = s * (1.f / 256.f);
    float var  = q * (1.f / 256.f) - mean * mean;
    float rstd = rsqrtf(var + 1e-3f);

    const float* ga = gamma + iter * DD;
    const float* be = beta + iter * DD;
    float4* xo = reinterpret_cast<float4*>(g_x + (size_t)row * DD);
    int c0 = lane * 4;
    float4 r0, r1;
    r0.x = (v0.x - mean) * rstd * ga[c0 + 0] + be[c0 + 0];
    r0.y = (v0.y - mean) * rstd * ga[c0 + 1] + be[c0 + 1];
    r0.z = (v0.z - mean) * rstd * ga[c0 + 2] + be[c0 + 2];
    r0.w = (v0.w - mean) * rstd * ga[c0 + 3] + be[c0 + 3];
    r1.x = (v1.x - mean) * rstd * ga[128 + c0 + 0] + be[128 + c0 + 0];
    r1.y = (v1.y - mean) * rstd * ga[128 + c0 + 1] + be[128 + c0 + 1];
    r1.z = (v1.z - mean) * rstd * ga[128 + c0 + 2] + be[128 + c0 + 2];
    r1.w = (v1.w - mean) * rstd * ga[128 + c0 + 3] + be[128 + c0 + 3];
    xo[lane] = r0;
    xo[32 + lane] = r1;
}

__global__ void k_zero() {
    int i = blockIdx.x * 256 + threadIdx.x;
    if (i < 196608) {
        reinterpret_cast<u32*>(g_hbh)[i] = 0u;
        reinterpret_cast<u32*>(g_hbl)[i] = 0u;
    }
    if (i == 0) g_sync = 0u;
}

// ---------------- persistent wavefront LSTM on HMMA ------------------------
#define LAP 36
#define LSTM_SMEM_U32 (32768 + 2 * 2 * 128 * LAP)
__global__ void __launch_bounds__(256, 1) k_lstm_mma(
    const float* __restrict__ blstm, float* __restrict__ out)
{
    extern __shared__ u32 sm[];
    u32* Bs = sm;
    u32* As = sm + 32768;

    const int bx    = blockIdx.x;
    const int ls    = bx >> 4;
    const int dir   = ls & 1;
    const int layer = ls >> 1;
    const int sub   = bx & 15;
    const int j0    = sub * 16;
    const int tid   = threadIdx.x;
    const int warp  = tid >> 5, lane = tid & 31;
    const int gid   = lane >> 2, tg = lane & 3;
    const int wm    = warp * 16;
    const int dl    = dir * 3 + layer;

    for (int i = tid; i < 8192; i += 256) {
        int plane = i >> 12, rem = i & 4095;
        int n = rem >> 6, c0 = (rem & 63) * 4;
        u32 dsw = (u32)c0 ^ (((u32)n & 7) << 2);
        u32 dst = smem_u32addr(Bs + plane * 16384 + n * 256 + dsw);
        const __nv_bfloat16* src = g_Wlb +
            ((size_t)(plane * 6 + dl) * 1024 + (j0 * 4 + n)) * 512 + c0 * 2;
        cp_async16(dst, src);
    }
    CP_COMMIT();

    float bias[8][4];
    float creg[8];
#pragma unroll
    for (int j8 = 0; j8 < 8; ++j8) {
        int cg = j0 + 2 * j8 + (tg >> 1);
        bias[j8][0] = blstm[dl * NG + 0 * 256 + cg];
        bias[j8][1] = blstm[dl * NG + 1 * 256 + cg];
        bias[j8][2] = blstm[dl * NG + 2 * 256 + cg];
        bias[j8][3] = blstm[dl * NG + 3 * 256 + cg];
        creg[j8] = 0.f;
    }
    const int ftm = tid >> 1;
    const int fko = (tid & 1) * 32;

    CP_WAIT0();
    __syncthreads();

    const unsigned nb = gridDim.x;
    const int lprev = (layer > 0) ? (layer - 1) : 0;
    const __nv_bfloat16* gxh = reinterpret_cast<const __nv_bfloat16*>(g_xh2);
    const __nv_bfloat16* gxl = reinterpret_cast<const __nv_bfloat16*>(g_xl2);

    for (int w = 0; w < TSEQ + 2; ++w) {
        const int t = w - layer;
        if (t >= 0 && t < TSEQ) {
            const int tt = dir ? (TSEQ - 1 - t) : t;
            const int rp = t & 1, wp = rp ^ 1;
            const int par = t & 1;
            const size_t curoffR = (size_t)((dir * 2 + lprev) * 2 + par) * BB * 256;
            const size_t curoffW = (size_t)((dir * 2 + layer) * 2 + par) * BB * 256;
            const size_t hoffR   = (size_t)(dl * 2 + rp) * BB * 256;
            const size_t hoffW   = (size_t)(dl * 2 + wp) * BB * 256;

            const __nv_bfloat16 *lowh, *lowl;
            if (layer == 0) {
                lowh = gxh + ((size_t)ftm * TSEQ + tt) * 256;
                lowl = gxl + ((size_t)ftm * TSEQ + tt) * 256;
            } else {
                lowh = g_cbh + curoffR + (size_t)ftm * 256;
                lowl = g_cbl + curoffR + (size_t)ftm * 256;
            }
            const __nv_bfloat16* hh_ = g_hbh + hoffR + (size_t)ftm * 256;
            const __nv_bfloat16* hl_ = g_hbl + hoffR + (size_t)ftm * 256;

            // residual prefetch from bf16 planes (hi+lo reconstruct)
            const int mrow = wm + gid + ((tg & 1) ? 8 : 0);
            float ainv[8];
#pragma unroll
            for (int j8 = 0; j8 < 8; ++j8) {
                int cg = j0 + 2 * j8 + (tg >> 1);
                if (layer == 0) {
                    size_t xi = ((size_t)mrow * TSEQ + tt) * 256 + cg;
                    ainv[j8] = __bfloat162float(gxh[xi]) + __bfloat162float(gxl[xi]);
                } else {
                    size_t ci = curoffR + (size_t)mrow * 256 + cg;
                    ainv[j8] = __bfloat162float(__ldcg(g_cbh + ci)) +
                               __bfloat162float(__ldcg(g_cbl + ci));
                }
            }

            float acc[8][4];
#pragma unroll
            for (int j8 = 0; j8 < 8; ++j8)
#pragma unroll
                for (int q = 0; q < 4; ++q) acc[j8][q] = 0.f;

#define STAGE(ci_, buf_) do {                                              \
    int kb_ = (ci_) * 64 + fko;                                            \
    const __nv_bfloat16 *sh_, *sl_;                                        \
    if (kb_ < 256) { sh_ = lowh + kb_; sl_ = lowl + kb_; }                 \
    else           { sh_ = hh_ + (kb_ - 256); sl_ = hl_ + (kb_ - 256); }   \
    u32 db_ = (buf_) * (2 * 128 * LAP) + ftm * LAP + (fko >> 1);           \
    _Pragma("unroll")                                                      \
    for (int j_ = 0; j_ < 4; ++j_)                                         \
        cp_async16(smem_u32addr(As + db_ + j_ * 4), sh_ + j_ * 8);         \
    db_ += 128 * LAP;                                                      \
    _Pragma("unroll")                                                      \
    for (int j_ = 0; j_ < 4; ++j_)                                         \
        cp_async16(smem_u32addr(As + db_ + j_ * 4), sl_ + j_ * 8);         \
} while (0)

            STAGE(0, 0); CP_COMMIT(); CP_WAIT0(); __syncthreads();

            for (int ci = 0; ci < 8; ++ci) {
                if (ci < 7) { STAGE(ci + 1, (ci + 1) & 1); CP_COMMIT(); }

                const u32* AhB = As + (ci & 1) * (2 * 128 * LAP);
                const u32* AlB = AhB + 128 * LAP;
                const int ra = (wm + gid) * LAP;
                const int rb = (wm + gid + 8) * LAP;
#pragma unroll
                for (int ks = 0; ks < 4; ++ks) {
                    const int pk = ks * 8 + tg;
                    u32 ah0 = AhB[ra + pk],     ah1 = AhB[rb + pk];
                    u32 ah2 = AhB[ra + pk + 4], ah3 = AhB[rb + pk + 4];
                    u32 al0 = AlB[ra + pk],     al1 = AlB[rb + pk];
                    u32 al2 = AlB[ra + pk + 4], al3 = AlB[rb + pk + 4];
                    const int kp = ci * 32 + ks * 8 + tg;
#pragma unroll
                    for (int j8 = 0; j8 < 8; ++j8) {
                        int nl = j8 * 8 + gid;
                        u32 xr = (u32)gid << 2;
                        const u32* bh = Bs + nl * 256;
                        const u32* bl = bh + 16384;
                        u32 b0h = bh[kp ^ xr], b1h = bh[(kp + 4) ^ xr];
                        u32 b0l = bl[kp ^ xr], b1l = bl[(kp + 4) ^ xr];
                        mma_bf16(acc[j8], ah0, ah1, ah2, ah3, b0h, b1h);
                        mma_bf16(acc[j8], ah0, ah1, ah2, ah3, b0l, b1l);
                        mma_bf16(acc[j8], al0, al1, al2, al3, b0h, b1h);
                    }
                }
                if (ci < 7) { CP_WAIT0(); __syncthreads(); }
            }
#undef STAGE

            // ---- epilogue: fast transcendentals, bf16-plane stores only ----
#pragma unroll
            for (int j8 = 0; j8 < 8; ++j8) {
                float c0 = acc[j8][0], c1 = acc[j8][1];
                float c2 = acc[j8][2], c3 = acc[j8][3];
                float sendA = (tg & 1) ? c0 : c2;
                float sendB = (tg & 1) ? c1 : c3;
                float rA = __shfl_xor_sync(0xffffffffu, sendA, 1);
                float rB = __shfl_xor_sync(0xffffffffu, sendB, 1);
                float zi, zf, zg, zo;
                if (!(tg & 1)) { zi = c0; zf = c1; zg = rA; zo = rB; }
                else           { zi = rA; zf = rB; zg = c2; zo = c3; }
                zi += bias[j8][0]; zf += bias[j8][1];
                zg += bias[j8][2]; zo += bias[j8][3];
                float ig = sigm(zi);
                float fg = sigm(zf);
                float gg = tanha(zg);
                float og = sigm(zo);
                float cn = fg * creg[j8] + ig * gg;
                float hn = og * tanha(cn);
                creg[j8] = cn;
                int cg = j0 + 2 * j8 + (tg >> 1);
                size_t hidx = hoffW + (size_t)mrow * 256 + cg;
                __nv_bfloat16 hh2 = __float2bfloat16(hn);
                g_hbh[hidx] = hh2;
                g_hbl[hidx] = __float2bfloat16(hn - __bfloat162float(hh2));
                if (t == TSEQ - 1) {
                    g_h[(size_t)(dl * 2 + wp) * BB * HH + (size_t)mrow * HH + cg] = hn;
                    g_c[(size_t)dl * BB * HH + (size_t)mrow * HH + cg] = cn;
                }
                float cu = ainv[j8] + hn;
                if (layer == 2) {
                    out[((size_t)mrow * TSEQ + tt) * 512 + dir * 256 + cg] = cu;
                } else {
                    size_t cidx = curoffW + (size_t)mrow * 256 + cg;
                    __nv_bfloat16 ch2 = __float2bfloat16(cu);
                    g_cbh[cidx] = ch2;
                    g_cbl[cidx] = __float2bfloat16(cu - __bfloat162float(ch2));
                }
            }
        }

        // ---- grid barrier ----
        __syncthreads();
        __threadfence();
        if (tid == 0) {
            atomicAdd(&g_sync, 1u);
            unsigned target = nb * (unsigned)(w + 1);
            while (*(volatile unsigned*)&g_sync < target) __nanosleep(64);
        }
        __syncthreads();
    }
}

// ---------------- final states ----------------
__global__ void k_states(float* __restrict__ out) {
    int idx = blockIdx.x * 256 + threadIdx.x;
    if (idx >= 2 * 3 * BB * HH) return;
    int j  = idx & 255;
    int m  = (idx >> 8) & 127;
    int dl = idx >> 15;
    const size_t SEQ = (size_t)BB * TSEQ * 512;
    const size_t SH  = 2 * 3 * BB * HH;
    out[SEQ + idx]      = g_h[(size_t)(dl * 2 + 0) * BB * HH + (size_t)m * HH + j];
    out[SEQ + SH + idx] = g_c[(size_t)dl * BB * HH + (size_t)m * HH + j];
}

// ---------------- launch ----------------
extern "C" void kernel_launch(void* const* d_in, const int* in_sizes, int n_in,
                              void* d_out, int out_size) {
    const int*   tokens = (const int*)d_in[0];
    const float* E      = (const float*)d_in[1];
    const float* W3     = (const float*)d_in[2];
    const float* W5     = (const float*)d_in[3];
    const float* W7     = (const float*)d_in[4];
    const float* bconv  = (const float*)d_in[5];
    const float* gamma  = (const float*)d_in[6];
    const float* beta   = (const float*)d_in[7];
    const float* Wx     = (const float*)d_in[8];
    const float* Wh     = (const float*)d_in[9];
    const float* blstm  = (const float*)d_in[10];
    float* out = (float*)d_out;

    const int SMEM_CONV = SM_CONV_U32 * 4;
    const int SMEM_LSTM = LSTM_SMEM_U32 * 4;
    static int s_attr = 0;
    if (!s_attr) {
        cudaFuncSetAttribute(k_conv_mma,
                             cudaFuncAttributeMaxDynamicSharedMemorySize, SMEM_CONV);
        cudaFuncSetAttribute(k_lstm_mma,
                             cudaFuncAttributeMaxDynamicSharedMemorySize, SMEM_LSTM);
        s_attr = 1;
    }

    k_embed<<<BB * TSEQ, 64>>>(tokens, E);
    k_wprep<<<(2 * 15 * 2 * 65536 + 255) / 256, 256>>>(W3, W5, W7);
    k_wprep_lstm<<<(int)((2ull * 6 * 1024 * 512 + 255) / 256), 256>>>(Wx, Wh);
    for (int it = 0; it < 2; ++it) {
        k_xsplit<<<(BB * TSEQ * 128) / 256, 256>>>();
        k_conv_mma<<<dim3(BB * 8, 4), 256, SMEM_CONV>>>(bconv, it);
        k_ln<<<BB * TSEQ / 8, 256>>>(gamma, beta, it);
    }
    k_xsplit<<<(BB * TSEQ * 128) / 256, 256>>>();
    k_zero<<<1536, 256>>>();
    k_lstm_mma<<<NBLK, 256, SMEM_LSTM>>>(blstm, out);
    k_states<<<768, 256>>>(out);
}

// round 14
// speedup vs baseline: 2.1375x; 1.0171x over previous
#include <cuda_runtime.h>
#include <cuda_bf16.h>
#include <math.h>
#include <cstdint>

#define BB   128
#define TSEQ 512
#define DD   256
#define HH   256
#define NG   1024
#define NBLK 96

typedef unsigned long long u64;
typedef unsigned int u32;

// ---- warp-level bf16 MMA (verified R11/R12) ----
__device__ __forceinline__ void mma_bf16(float* c, u32 a0, u32 a1, u32 a2, u32 a3,
                                         u32 b0, u32 b1) {
    asm volatile(
        "mma.sync.aligned.m16n8k16.row.col.f32.bf16.bf16.f32 "
        "{%0,%1,%2,%3}, {%4,%5,%6,%7}, {%8,%9}, {%0,%1,%2,%3};"
        : "+f"(c[0]), "+f"(c[1]), "+f"(c[2]), "+f"(c[3])
        : "r"(a0), "r"(a1), "r"(a2), "r"(a3), "r"(b0), "r"(b1));
}
__device__ __forceinline__ u32 smem_u32addr(const void* p) {
    u32 a;
    asm("{ .reg .u64 t; cvta.to.shared.u64 t, %1; cvt.u32.u64 %0, t; }" : "=r"(a) : "l"(p));
    return a;
}
__device__ __forceinline__ void cp_async16(u32 dst, const void* src) {
    asm volatile("cp.async.cg.shared.global [%0], [%1], 16;" :: "r"(dst), "l"(src));
}
#define CP_COMMIT() asm volatile("cp.async.commit_group;" ::: "memory")
#define CP_WAIT0()  asm volatile("cp.async.wait_group 0;" ::: "memory")
__device__ __forceinline__ float tanha(float x) {
    float r; asm("tanh.approx.f32 %0, %1;" : "=f"(r) : "f"(x)); return r;
}
__device__ __forceinline__ float sigm(float x) {
    return 0.5f + 0.5f * tanha(0.5f * x);
}

// ---------------- device scratch ----------------
__device__ float g_x[BB * TSEQ * DD];
__device__ float g_feats[BB * TSEQ * DD];
__device__ float g_h[2 * 3 * 2 * BB * HH];
__device__ float g_c[2 * 3 * BB * HH];
__device__ unsigned g_sync;
__device__ u32 g_xh2[BB * TSEQ * 128];
__device__ u32 g_xl2[BB * TSEQ * 128];
__device__ u32 g_Wb2[2 * 15 * 2 * 32768];
__device__ __nv_bfloat16 g_Wlb[2ull * 6 * 1024 * 512];
__device__ __nv_bfloat16 g_hbh[6 * 2 * BB * 256];
__device__ __nv_bfloat16 g_hbl[6 * 2 * BB * 256];
__device__ __nv_bfloat16 g_cbh[2 * 2 * 2 * BB * 256];
__device__ __nv_bfloat16 g_cbl[2 * 2 * 2 * BB * 256];

// ---------------- embedding gather ----------------
__global__ void k_embed(const int* __restrict__ tokens, const float* __restrict__ E) {
    int row = blockIdx.x;
    int tok = tokens[row];
    const float4* src = reinterpret_cast<const float4*>(E) + (size_t)tok * (DD / 4);
    float4* dst = reinterpret_cast<float4*>(g_x) + (size_t)row * (DD / 4);
    dst[threadIdx.x] = src[threadIdx.x];
}

// ---------------- conv W pack ----------------
__global__ void k_wprep(const float* __restrict__ W3, const float* __restrict__ W5,
                        const float* __restrict__ W7) {
    int idx = blockIdx.x * 256 + threadIdx.x;
    const int TOT = 2 * 15 * 2 * 65536;
    if (idx >= TOT) return;
    int k     = idx & 255;
    int n     = (idx >> 8) & 255;
    int plane = (idx >> 16) & 1;
    int tp    = idx >> 17;
    int tap   = tp % 15;
    int iter  = tp / 15;
    const float* Wsrc; int kk, KW;
    if (tap < 3)      { Wsrc = W3; kk = tap;     KW = 3; }
    else if (tap < 8) { Wsrc = W5; kk = tap - 3; KW = 5; }
    else              { Wsrc = W7; kk = tap - 8; KW = 7; }
    float v = Wsrc[(((size_t)iter * KW + kk) * 256 + k) * 256 + n];
    __nv_bfloat16 hi = __float2bfloat16(v);
    __nv_bfloat16 val = plane ? __float2bfloat16(v - __bfloat162float(hi)) : hi;
    __nv_bfloat16* dst = reinterpret_cast<__nv_bfloat16*>(g_Wb2);
    dst[(size_t)(((iter * 15 + tap) * 2 + plane)) * 65536 + n * 256 + k] = val;
}

// ---------------- LSTM W pack ----------
__global__ void k_wprep_lstm(const float* __restrict__ Wx, const float* __restrict__ Wh) {
    size_t idx = (size_t)blockIdx.x * 256 + threadIdx.x;
    const size_t TOT = 2ull * 6 * 1024 * 512;
    if (idx >= TOT) return;
    int k     = (int)(idx & 511);
    int n     = (int)((idx >> 9) & 1023);
    int dl    = (int)((idx >> 19) % 6);
    int plane = (int)(idx / (6ull << 19));
    int col = n >> 2, g = n & 3;
    int nc = g * 256 + col;
    float v = (k < 256) ? Wx[(size_t)dl * 256 * NG + (size_t)k * NG + nc]
                        : Wh[(size_t)dl * 256 * NG + (size_t)(k - 256) * NG + nc];
    __nv_bfloat16 hi = __float2bfloat16(v);
    __nv_bfloat16 val = plane ? __float2bfloat16(v - __bfloat162float(hi)) : hi;
    g_Wlb[idx] = val;
}

// ---------------- x split ----------
__global__ void k_xsplit() {
    size_t idx = (size_t)blockIdx.x * 256 + threadIdx.x;
    float a0 = g_x[idx * 2], a1 = g_x[idx * 2 + 1];
    __nv_bfloat16 h0 = __float2bfloat16(a0), h1 = __float2bfloat16(a1);
    __nv_bfloat16 l0 = __float2bfloat16(a0 - __bfloat162float(h0));
    __nv_bfloat16 l1 = __float2bfloat16(a1 - __bfloat162float(h1));
    __nv_bfloat162 hp; hp.x = h0; hp.y = h1;
    __nv_bfloat162 lp; lp.x = l0; lp.y = l1;
    g_xh2[idx] = *reinterpret_cast<u32*>(&hp);
    g_xl2[idx] = *reinterpret_cast<u32*>(&lp);
}

// ---------------- conv bank on HMMA (unchanged, passing) ----------
#define CAP 132
#define SM_AL 9240
#define SM_B  18480
#define SM_CONV_U32 (18480 + 32768)
#define B_CHUNKS 4096
__global__ void __launch_bounds__(256, 1) k_conv_mma(
    const float* __restrict__ bconv, int iter)
{
    extern __shared__ u32 sm[];
    u32* Ah = sm;
    u32* Al = sm + SM_AL;
    u32* Bb = sm + SM_B;

    const int tid  = threadIdx.x;
    const int warp = tid >> 5, lane = tid & 31;
    const int gid  = lane >> 2, tg = lane & 3;
    const int b    = blockIdx.x >> 3;
    const int t0   = (blockIdx.x & 7) * 64;
    const int n0   = blockIdx.y * 64;
    const int wm   = (warp & 3) * 16;
    const int wn   = (warp >> 2) * 32;

    for (int idx = tid; idx < 70 * 128; idx += 256) {
        int r = idx >> 7, c = idx & 127;
        int t = t0 - 3 + r;
        u32 vh = 0, vl = 0;
        if (t >= 0 && t < TSEQ) {
            size_t g = ((size_t)b * TSEQ + t) * 128 + c;
            vh = g_xh2[g]; vl = g_xl2[g];
        }
        Ah[r * CAP + c] = vh;
        Al[r * CAP + c] = vl;
    }

    const size_t wbase = (size_t)(iter * 15) * 2 * 32768;
    {
        for (int i = tid; i < B_CHUNKS; i += 256) {
            int p = i >> 11, rem = i & 2047;
            int n = rem >> 5, cq = rem & 31;
            int c0 = cq * 4;
            u32 dsw = (u32)c0 ^ (((u32)n & 7) << 2);
            u32 dst = smem_u32addr(Bb + p * 8192 + n * 128 + dsw);
            const u32* src = g_Wb2 + wbase + (size_t)p * 32768 + (size_t)(n0 + n) * 128 + c0;
            cp_async16(dst, src);
        }
        CP_COMMIT();
    }
    CP_WAIT0();
    __syncthreads();

    float acc[3][4][4];
#pragma unroll
    for (int w = 0; w < 3; ++w)
#pragma unroll
        for (int j = 0; j < 4; ++j)
#pragma unroll
            for (int q = 0; q < 4; ++q) acc[w][j][q] = 0.f;

    for (int tap = 0; tap < 15; ++tap) {
        int widx, kk;
        if (tap < 3)      { widx = 0; kk = tap; }
        else if (tap < 8) { widx = 1; kk = tap - 3; }
        else              { widx = 2; kk = tap - 8; }
        const int shift = kk - widx - 1;
        const int buf = tap & 1;

        if (tap < 14) {
            const size_t nb = (size_t)((iter * 15 + tap + 1) * 2) * 32768;
            u32* Bo = Bb + (buf ^ 1) * 16384;
            for (int i = tid; i < B_CHUNKS; i += 256) {
                int p = i >> 11, rem = i & 2047;
                int n = rem >> 5, cq = rem & 31;
                int c0 = cq * 4;
                u32 dsw = (u32)c0 ^ (((u32)n & 7) << 2);
                u32 dst = smem_u32addr(Bo + p * 8192 + n * 128 + dsw);
                const u32* src = g_Wb2 + nb + (size_t)p * 32768 + (size_t)(n0 + n) * 128 + c0;
                cp_async16(dst, src);
            }
            CP_COMMIT();
        }

        const u32* Bh = Bb + buf * 16384;
        const u32* Bl = Bh + 8192;
        const int r0 = 3 + shift + wm + gid;
        const u32* arh0 = Ah + r0 * CAP;
        const u32* arh1 = arh0 + 8 * CAP;
        const u32* arl0 = Al + r0 * CAP;
        const u32* arl1 = arl0 + 8 * CAP;
        float* accw = &acc[widx][0][0];

#pragma unroll
        for (int ks = 0; ks < 16; ++ks) {
            const int kc2 = ks * 8;
            u32 ah0 = arh0[kc2 + tg],     ah1 = arh1[kc2 + tg];
            u32 ah2 = arh0[kc2 + tg + 4], ah3 = arh1[kc2 + tg + 4];
            u32 al0 = arl0[kc2 + tg],     al1 = arl1[kc2 + tg];
            u32 al2 = arl0[kc2 + tg + 4], al3 = arl1[kc2 + tg + 4];
#pragma unroll
            for (int j8 = 0; j8 < 4; ++j8) {
                int nl = wn + j8 * 8 + gid;
                u32 xr = ((u32)(nl & 7)) << 2;
                const u32* bhp = Bh + nl * 128;
                const u32* blp = Bl + nl * 128;
                u32 bh0 = bhp[(kc2 + tg) ^ xr];
                u32 bh1 = bhp[(kc2 + tg + 4) ^ xr];
                u32 bl0 = blp[(kc2 + tg) ^ xr];
                u32 bl1 = blp[(kc2 + tg + 4) ^ xr];
                float* cc = accw + j8 * 4;
                mma_bf16(cc, ah0, ah1, ah2, ah3, bh0, bh1);
                mma_bf16(cc, ah0, ah1, ah2, ah3, bl0, bl1);
                mma_bf16(cc, al0, al1, al2, al3, bh0, bh1);
            }
        }

        if (tap < 14) {
            CP_WAIT0();
            __syncthreads();
        }
    }

    {
        const float* b3 = bconv + (iter * 3 + 0) * 256 + n0;
        const float* b5 = bconv + (iter * 3 + 1) * 256 + n0;
        const float* b7 = bconv + (iter * 3 + 2) * 256 + n0;
        const int trow = t0 + wm + gid;
#pragma unroll
        for (int j8 = 0; j8 < 4; ++j8) {
            int cl = wn + j8 * 8 + tg * 2;
            float bb3a = b3[cl], bb3b = b3[cl + 1];
            float bb5a = b5[cl], bb5b = b5[cl + 1];
            float bb7a = b7[cl], bb7b = b7[cl + 1];
#pragma unroll
            for (int rh = 0; rh < 2; ++rh) {
                size_t row = (size_t)b * TSEQ + trow + rh * 8;
                const float2 xv = *reinterpret_cast<const float2*>(
                    g_x + row * 256 + n0 + cl);
                float c3a = acc[0][j8][rh * 2 + 0], c3b = acc[0][j8][rh * 2 + 1];
                float c5a = acc[1][j8][rh * 2 + 0], c5b = acc[1][j8][rh * 2 + 1];
                float c7a = acc[2][j8][rh * 2 + 0], c7b = acc[2][j8][rh * 2 + 1];
                float2 o;
                o.x = tanha(c3a + bb3a) + tanha(c5a + bb5a) + tanha(c7a + bb7a) + xv.x;
                o.y = tanha(c3b + bb3b) + tanha(c5b + bb5b) + tanha(c7b + bb7b) + xv.y;
                *reinterpret_cast<float2*>(g_feats + row * 256 + n0 + cl) = o;
            }
        }
    }
}

// ---------------- layernorm ----------------
__global__ void k_ln(const float* __restrict__ gamma, const float* __restrict__ beta, int iter) {
    int wid = threadIdx.x >> 5, lane = threadIdx.x & 31;
    int row = blockIdx.x * 8 + wid;
    const float4* f = reinterpret_cast<const float4*>(g_feats + (size_t)row * DD);
    float4 v0 = f[lane];
    float4 v1 = f[32 + lane];
    float s = v0.x + v0.y + v0.z + v0.w + v1.x + v1.y + v1.z + v1.w;
    float q = v0.x*v0.x + v0.y*v0.y + v0.z*v0.z + v0.w*v0.w +
              v1.x*v1.x + v1.y*v1.y + v1.z*v1.z + v1.w*v1.w;
#pragma unroll
    for (int ofs = 16; ofs; ofs >>= 1) {
        s += __shfl_xor_sync(0xffffffffu, s, ofs);
        q += __shfl_xor_sync(0xffffffffu, q, ofs);
    }
    float mean = s * (1.f / 256.f);
    float var  = q * (1.f / 256.f) - mean * mean;
    float rstd = rsqrtf(var + 1e-3f);

    const float* ga = gamma + iter * DD;
    const float* be = beta + iter * DD;
    float4* xo = reinterpret_cast<float4*>(g_x + (size_t)row * DD);
    int c0 = lane * 4;
    float4 r0, r1;
    r0.x = (v0.x - mean) * rstd * ga[c0 + 0] + be[c0 + 0];
    r0.y = (v0.y - mean) * rstd * ga[c0 + 1] + be[c0 + 1];
    r0.z = (v0.z - mean) * rstd * ga[c0 + 2] + be[c0 + 2];
    r0.w = (v0.w - mean) * rstd * ga[c0 + 3] + be[c0 + 3];
    r1.x = (v1.x - mean) * rstd * ga[128 + c0 + 0] + be[128 + c0 + 0];
    r1.y = (v1.y - mean) * rstd * ga[128 + c0 + 1] + be[128 + c0 + 1];
    r1.z = (v1.z - mean) * rstd * ga[128 + c0 + 2] + be[128 + c0 + 2];
    r1.w = (v1.w - mean) * rstd * ga[128 + c0 + 3] + be[128 + c0 + 3];
    xo[lane] = r0;
    xo[32 + lane] = r1;
}

__global__ void k_zero() {
    int i = blockIdx.x * 256 + threadIdx.x;
    if (i < 196608) {
        reinterpret_cast<u32*>(g_hbh)[i] = 0u;
        reinterpret_cast<u32*>(g_hbl)[i] = 0u;
    }
    if (i == 0) g_sync = 0u;
}

// ---------------- persistent wavefront LSTM on HMMA (32m x 32n warp tiles) --
#define LAP 36
#define LSTM_SMEM_U32 (32768 + 2 * 2 * 128 * LAP)
__global__ void __launch_bounds__(256, 1) k_lstm_mma(
    const float* __restrict__ blstm, float* __restrict__ out)
{
    extern __shared__ u32 sm[];
    u32* Bs = sm;
    u32* As = sm + 32768;

    const int bx    = blockIdx.x;
    const int ls    = bx >> 4;
    const int dir   = ls & 1;
    const int layer = ls >> 1;
    const int sub   = bx & 15;
    const int j0    = sub * 16;
    const int tid   = threadIdx.x;
    const int warp  = tid >> 5, lane = tid & 31;
    const int gid   = lane >> 2, tg = lane & 3;
    const int mgrp  = warp & 3;          // 4 m-groups of 32 rows
    const int ngrp  = warp >> 2;         // 2 n-groups of 32 (4 j8-tiles each)
    const int m0    = mgrp * 32;
    const int dl    = dir * 3 + layer;

    for (int i = tid; i < 8192; i += 256) {
        int plane = i >> 12, rem = i & 4095;
        int n = rem >> 6, c0 = (rem & 63) * 4;
        u32 dsw = (u32)c0 ^ (((u32)n & 7) << 2);
        u32 dst = smem_u32addr(Bs + plane * 16384 + n * 256 + dsw);
        const __nv_bfloat16* src = g_Wlb +
            ((size_t)(plane * 6 + dl) * 1024 + (j0 * 4 + n)) * 512 + c0 * 2;
        cp_async16(dst, src);
    }
    CP_COMMIT();

    // per-thread constants: 4 cols (j4), both m-tiles share them
    float bias[4][4];
    float creg[2][4];
#pragma unroll
    for (int j4 = 0; j4 < 4; ++j4) {
        int cg = j0 + 2 * (ngrp * 4 + j4) + (tg >> 1);
        bias[j4][0] = blstm[dl * NG + 0 * 256 + cg];
        bias[j4][1] = blstm[dl * NG + 1 * 256 + cg];
        bias[j4][2] = blstm[dl * NG + 2 * 256 + cg];
        bias[j4][3] = blstm[dl * NG + 3 * 256 + cg];
        creg[0][j4] = 0.f; creg[1][j4] = 0.f;
    }
    const int ftm = tid >> 1;
    const int fko = (tid & 1) * 32;
    int mrow[2];
    mrow[0] = m0 + gid + ((tg & 1) ? 8 : 0);
    mrow[1] = mrow[0] + 16;

    CP_WAIT0();
    __syncthreads();

    const unsigned nb = gridDim.x;
    const int lprev = (layer > 0) ? (layer - 1) : 0;
    const __nv_bfloat16* gxh = reinterpret_cast<const __nv_bfloat16*>(g_xh2);
    const __nv_bfloat16* gxl = reinterpret_cast<const __nv_bfloat16*>(g_xl2);

    for (int w = 0; w < TSEQ + 2; ++w) {
        const int t = w - layer;
        if (t >= 0 && t < TSEQ) {
            const int tt = dir ? (TSEQ - 1 - t) : t;
            const int rp = t & 1, wp = rp ^ 1;
            const int par = t & 1;
            const size_t curoffR = (size_t)((dir * 2 + lprev) * 2 + par) * BB * 256;
            const size_t curoffW = (size_t)((dir * 2 + layer) * 2 + par) * BB * 256;
            const size_t hoffR   = (size_t)(dl * 2 + rp) * BB * 256;
            const size_t hoffW   = (size_t)(dl * 2 + wp) * BB * 256;

            const __nv_bfloat16 *lowh, *lowl;
            if (layer == 0) {
                lowh = gxh + ((size_t)ftm * TSEQ + tt) * 256;
                lowl = gxl + ((size_t)ftm * TSEQ + tt) * 256;
            } else {
                lowh = g_cbh + curoffR + (size_t)ftm * 256;
                lowl = g_cbl + curoffR + (size_t)ftm * 256;
            }
            const __nv_bfloat16* hh_ = g_hbh + hoffR + (size_t)ftm * 256;
            const __nv_bfloat16* hl_ = g_hbl + hoffR + (size_t)ftm * 256;

            // residual prefetch (2 m-rows x 4 cols)
            float ainv[2][4];
#pragma unroll
            for (int mt = 0; mt < 2; ++mt)
#pragma unroll
            for (int j4 = 0; j4 < 4; ++j4) {
                int cg = j0 + 2 * (ngrp * 4 + j4) + (tg >> 1);
                if (layer == 0) {
                    size_t xi = ((size_t)mrow[mt] * TSEQ + tt) * 256 + cg;
                    ainv[mt][j4] = __bfloat162float(gxh[xi]) + __bfloat162float(gxl[xi]);
                } else {
                    size_t ci = curoffR + (size_t)mrow[mt] * 256 + cg;
                    ainv[mt][j4] = __bfloat162float(__ldcg(g_cbh + ci)) +
                                   __bfloat162float(__ldcg(g_cbl + ci));
                }
            }

            float acc[2][4][4];
#pragma unroll
            for (int mt = 0; mt < 2; ++mt)
#pragma unroll
                for (int j4 = 0; j4 < 4; ++j4)
#pragma unroll
                    for (int q = 0; q < 4; ++q) acc[mt][j4][q] = 0.f;

#define STAGE(ci_, buf_) do {                                              \
    int kb_ = (ci_) * 64 + fko;                                            \
    const __nv_bfloat16 *sh_, *sl_;                                        \
    if (kb_ < 256) { sh_ = lowh + kb_; sl_ = lowl + kb_; }                 \
    else           { sh_ = hh_ + (kb_ - 256); sl_ = hl_ + (kb_ - 256); }   \
    u32 db_ = (buf_) * (2 * 128 * LAP) + ftm * LAP + (fko >> 1);           \
    _Pragma("unroll")                                                      \
    for (int j_ = 0; j_ < 4; ++j_)                                         \
        cp_async16(smem_u32addr(As + db_ + j_ * 4), sh_ + j_ * 8);         \
    db_ += 128 * LAP;                                                      \
    _Pragma("unroll")                                                      \
    for (int j_ = 0; j_ < 4; ++j_)                                         \
        cp_async16(smem_u32addr(As + db_ + j_ * 4), sl_ + j_ * 8);         \
} while (0)

            STAGE(0, 0); CP_COMMIT(); CP_WAIT0(); __syncthreads();

            for (int ci = 0; ci < 8; ++ci) {
                if (ci < 7) { STAGE(ci + 1, (ci + 1) & 1); CP_COMMIT(); }

                const u32* AhB = As + (ci & 1) * (2 * 128 * LAP);
                const u32* AlB = AhB + 128 * LAP;
#pragma unroll
                for (int ks = 0; ks < 4; ++ks) {
                    const int pk = ks * 8 + tg;
                    const int kp = ci * 32 + pk;
                    u32 ah[2][4], al[2][4];
#pragma unroll
                    for (int mt = 0; mt < 2; ++mt) {
                        const int ra = (m0 + mt * 16 + gid) * LAP;
                        const int rb = ra + 8 * LAP;
                        ah[mt][0] = AhB[ra + pk];     ah[mt][1] = AhB[rb + pk];
                        ah[mt][2] = AhB[ra + pk + 4]; ah[mt][3] = AhB[rb + pk + 4];
                        al[mt][0] = AlB[ra + pk];     al[mt][1] = AlB[rb + pk];
                        al[mt][2] = AlB[ra + pk + 4]; al[mt][3] = AlB[rb + pk + 4];
                    }
#pragma unroll
                    for (int j4 = 0; j4 < 4; ++j4) {
                        int nl = ngrp * 32 + j4 * 8 + gid;
                        u32 xr = (u32)(nl & 7) << 2;
                        const u32* bh = Bs + nl * 256;
                        const u32* bl = bh + 16384;
                        u32 b0h = bh[kp ^ xr], b1h = bh[(kp + 4) ^ xr];
                        u32 b0l = bl[kp ^ xr], b1l = bl[(kp + 4) ^ xr];
#pragma unroll
                        for (int mt = 0; mt < 2; ++mt) {
                            mma_bf16(acc[mt][j4], ah[mt][0], ah[mt][1], ah[mt][2], ah[mt][3], b0h, b1h);
                            mma_bf16(acc[mt][j4], ah[mt][0], ah[mt][1], ah[mt][2], ah[mt][3], b0l, b1l);
                            mma_bf16(acc[mt][j4], al[mt][0], al[mt][1], al[mt][2], al[mt][3], b0h, b1h);
                        }
                    }
                }
                if (ci < 7) { CP_WAIT0(); __syncthreads(); }
            }
#undef STAGE

            // ---- epilogue ----
#pragma unroll
            for (int mt = 0; mt < 2; ++mt)
#pragma unroll
            for (int j4 = 0; j4 < 4; ++j4) {
                float c0 = acc[mt][j4][0], c1 = acc[mt][j4][1];
                float c2 = acc[mt][j4][2], c3 = acc[mt][j4][3];
                float sendA = (tg & 1) ? c0 : c2;
                float sendB = (tg & 1) ? c1 : c3;
                float rA = __shfl_xor_sync(0xffffffffu, sendA, 1);
                float rB = __shfl_xor_sync(0xffffffffu, sendB, 1);
                float zi, zf, zg, zo;
                if (!(tg & 1)) { zi = c0; zf = c1; zg = rA; zo = rB; }
                else           { zi = rA; zf = rB; zg = c2; zo = c3; }
                zi += bias[j4][0]; zf += bias[j4][1];
                zg += bias[j4][2]; zo += bias[j4][3];
                float ig = sigm(zi);
                float fg = sigm(zf);
                float gg = tanha(zg);
                float og = sigm(zo);
                float cn = fg * creg[mt][j4] + ig * gg;
                float hn = og * tanha(cn);
                creg[mt][j4] = cn;
                int cg = j0 + 2 * (ngrp * 4 + j4) + (tg >> 1);
                int m = mrow[mt];
                size_t hidx = hoffW + (size_t)m * 256 + cg;
                __nv_bfloat16 hh2 = __float2bfloat16(hn);
                g_hbh[hidx] = hh2;
                g_hbl[hidx] = __float2bfloat16(hn - __bfloat162float(hh2));
                if (t == TSEQ - 1) {
                    g_h[(size_t)(dl * 2 + wp) * BB * HH + (size_t)m * HH + cg] = hn;
                    g_c[(size_t)dl * BB * HH + (size_t)m * HH + cg] = cn;
                }
                float cu = ainv[mt][j4] + hn;
                if (layer == 2) {
                    out[((size_t)m * TSEQ + tt) * 512 + dir * 256 + cg] = cu;
                } else {
                    size_t cidx = curoffW + (size_t)m * 256 + cg;
                    __nv_bfloat16 ch2 = __float2bfloat16(cu);
                    g_cbh[cidx] = ch2;
                    g_cbl[cidx] = __float2bfloat16(cu - __bfloat162float(ch2));
                }
            }
        }

        // ---- grid barrier ----
        __syncthreads();
        __threadfence();
        if (tid == 0) {
            atomicAdd(&g_sync, 1u);
            unsigned target = nb * (unsigned)(w + 1);
            while (*(volatile unsigned*)&g_sync < target) __nanosleep(64);
        }
        __syncthreads();
    }
}

// ---------------- final states ----------------
__global__ void k_states(float* __restrict__ out) {
    int idx = blockIdx.x * 256 + threadIdx.x;
    if (idx >= 2 * 3 * BB * HH) return;
    int j  = idx & 255;
    int m  = (idx >> 8) & 127;
    int dl = idx >> 15;
    const size_t SEQ = (size_t)BB * TSEQ * 512;
    const size_t SH  = 2 * 3 * BB * HH;
    out[SEQ + idx]      = g_h[(size_t)(dl * 2 + 0) * BB * HH + (size_t)m * HH + j];
    out[SEQ + SH + idx] = g_c[(size_t)dl * BB * HH + (size_t)m * HH + j];
}

// ---------------- launch ----------------
extern "C" void kernel_launch(void* const* d_in, const int* in_sizes, int n_in,
                              void* d_out, int out_size) {
    const int*   tokens = (const int*)d_in[0];
    const float* E      = (const float*)d_in[1];
    const float* W3     = (const float*)d_in[2];
    const float* W5     = (const float*)d_in[3];
    const float* W7     = (const float*)d_in[4];
    const float* bconv  = (const float*)d_in[5];
    const float* gamma  = (const float*)d_in[6];
    const float* beta   = (const float*)d_in[7];
    const float* Wx     = (const float*)d_in[8];
    const float* Wh     = (const float*)d_in[9];
    const float* blstm  = (const float*)d_in[10];
    float* out = (float*)d_out;

    const int SMEM_CONV = SM_CONV_U32 * 4;
    const int SMEM_LSTM = LSTM_SMEM_U32 * 4;
    static int s_attr = 0;
    if (!s_attr) {
        cudaFuncSetAttribute(k_conv_mma,
                             cudaFuncAttributeMaxDynamicSharedMemorySize, SMEM_CONV);
        cudaFuncSetAttribute(k_lstm_mma,
                             cudaFuncAttributeMaxDynamicSharedMemorySize, SMEM_LSTM);
        s_attr = 1;
    }

    k_embed<<<BB * TSEQ, 64>>>(tokens, E);
    k_wprep<<<(2 * 15 * 2 * 65536 + 255) / 256, 256>>>(W3, W5, W7);
    k_wprep_lstm<<<(int)((2ull * 6 * 1024 * 512 + 255) / 256), 256>>>(Wx, Wh);
    for (int it = 0; it < 2; ++it) {
        k_xsplit<<<(BB * TSEQ * 128) / 256, 256>>>();
        k_conv_mma<<<dim3(BB * 8, 4), 256, SMEM_CONV>>>(bconv, it);
        k_ln<<<BB * TSEQ / 8, 256>>>(gamma, beta, it);
    }
    k_xsplit<<<(BB * TSEQ * 128) / 256, 256>>>();
    k_zero<<<1536, 256>>>();
    k_lstm_mma<<<NBLK, 256, SMEM_LSTM>>>(blstm, out);
    k_states<<<768, 256>>>(out);
}

// round 15
// speedup vs baseline: 2.2737x; 1.0637x over previous
#include <cuda_runtime.h>
#include <cuda_bf16.h>
#include <math.h>
#include <cstdint>

#define BB   128
#define TSEQ 512
#define DD   256
#define HH   256
#define NG   1024
#define NBLK 96

typedef unsigned long long u64;
typedef unsigned int u32;

// ---- warp-level bf16 MMA (verified R11/R12) ----
__device__ __forceinline__ void mma_bf16(float* c, u32 a0, u32 a1, u32 a2, u32 a3,
                                         u32 b0, u32 b1) {
    asm volatile(
        "mma.sync.aligned.m16n8k16.row.col.f32.bf16.bf16.f32 "
        "{%0,%1,%2,%3}, {%4,%5,%6,%7}, {%8,%9}, {%0,%1,%2,%3};"
        : "+f"(c[0]), "+f"(c[1]), "+f"(c[2]), "+f"(c[3])
        : "r"(a0), "r"(a1), "r"(a2), "r"(a3), "r"(b0), "r"(b1));
}
__device__ __forceinline__ u32 smem_u32addr(const void* p) {
    u32 a;
    asm("{ .reg .u64 t; cvta.to.shared.u64 t, %1; cvt.u32.u64 %0, t; }" : "=r"(a) : "l"(p));
    return a;
}
__device__ __forceinline__ void cp_async16(u32 dst, const void* src) {
    asm volatile("cp.async.cg.shared.global [%0], [%1], 16;" :: "r"(dst), "l"(src));
}
#define CP_COMMIT() asm volatile("cp.async.commit_group;" ::: "memory")
#define CP_WAIT0()  asm volatile("cp.async.wait_group 0;" ::: "memory")
__device__ __forceinline__ float tanha(float x) {
    float r; asm("tanh.approx.f32 %0, %1;" : "=f"(r) : "f"(x)); return r;
}
__device__ __forceinline__ float sigm(float x) {
    return 0.5f + 0.5f * tanha(0.5f * x);
}

// ---------------- device scratch ----------------
__device__ float g_x[BB * TSEQ * DD];
__device__ float g_feats[BB * TSEQ * DD];
__device__ float g_h[2 * 3 * 2 * BB * HH];
__device__ float g_c[2 * 3 * BB * HH];
__device__ unsigned g_sync;
__device__ u32 g_xh2[BB * TSEQ * 128];
__device__ u32 g_xl2[BB * TSEQ * 128];
__device__ u32 g_Wb2[2 * 15 * 2 * 32768];
__device__ __nv_bfloat16 g_Wlb[2ull * 6 * 1024 * 512];
__device__ __nv_bfloat16 g_hbh[6 * 2 * BB * 256];
__device__ __nv_bfloat16 g_hbl[6 * 2 * BB * 256];
__device__ __nv_bfloat16 g_cbh[2 * 2 * 2 * BB * 256];
__device__ __nv_bfloat16 g_cbl[2 * 2 * 2 * BB * 256];

// ---------------- embedding gather ----------------
__global__ void k_embed(const int* __restrict__ tokens, const float* __restrict__ E) {
    int row = blockIdx.x;
    int tok = tokens[row];
    const float4* src = reinterpret_cast<const float4*>(E) + (size_t)tok * (DD / 4);
    float4* dst = reinterpret_cast<float4*>(g_x) + (size_t)row * (DD / 4);
    dst[threadIdx.x] = src[threadIdx.x];
}

// ---------------- conv W pack ----------------
__global__ void k_wprep(const float* __restrict__ W3, const float* __restrict__ W5,
                        const float* __restrict__ W7) {
    int idx = blockIdx.x * 256 + threadIdx.x;
    const int TOT = 2 * 15 * 2 * 65536;
    if (idx >= TOT) return;
    int k     = idx & 255;
    int n     = (idx >> 8) & 255;
    int plane = (idx >> 16) & 1;
    int tp    = idx >> 17;
    int tap   = tp % 15;
    int iter  = tp / 15;
    const float* Wsrc; int kk, KW;
    if (tap < 3)      { Wsrc = W3; kk = tap;     KW = 3; }
    else if (tap < 8) { Wsrc = W5; kk = tap - 3; KW = 5; }
    else              { Wsrc = W7; kk = tap - 8; KW = 7; }
    float v = Wsrc[(((size_t)iter * KW + kk) * 256 + k) * 256 + n];
    __nv_bfloat16 hi = __float2bfloat16(v);
    __nv_bfloat16 val = plane ? __float2bfloat16(v - __bfloat162float(hi)) : hi;
    __nv_bfloat16* dst = reinterpret_cast<__nv_bfloat16*>(g_Wb2);
    dst[(size_t)(((iter * 15 + tap) * 2 + plane)) * 65536 + n * 256 + k] = val;
}

// ---------------- LSTM W pack ----------
__global__ void k_wprep_lstm(const float* __restrict__ Wx, const float* __restrict__ Wh) {
    size_t idx = (size_t)blockIdx.x * 256 + threadIdx.x;
    const size_t TOT = 2ull * 6 * 1024 * 512;
    if (idx >= TOT) return;
    int k     = (int)(idx & 511);
    int n     = (int)((idx >> 9) & 1023);
    int dl    = (int)((idx >> 19) % 6);
    int plane = (int)(idx / (6ull << 19));
    int col = n >> 2, g = n & 3;
    int nc = g * 256 + col;
    float v = (k < 256) ? Wx[(size_t)dl * 256 * NG + (size_t)k * NG + nc]
                        : Wh[(size_t)dl * 256 * NG + (size_t)(k - 256) * NG + nc];
    __nv_bfloat16 hi = __float2bfloat16(v);
    __nv_bfloat16 val = plane ? __float2bfloat16(v - __bfloat162float(hi)) : hi;
    g_Wlb[idx] = val;
}

// ---------------- x split ----------
__global__ void k_xsplit() {
    size_t idx = (size_t)blockIdx.x * 256 + threadIdx.x;
    float a0 = g_x[idx * 2], a1 = g_x[idx * 2 + 1];
    __nv_bfloat16 h0 = __float2bfloat16(a0), h1 = __float2bfloat16(a1);
    __nv_bfloat16 l0 = __float2bfloat16(a0 - __bfloat162float(h0));
    __nv_bfloat16 l1 = __float2bfloat16(a1 - __bfloat162float(h1));
    __nv_bfloat162 hp; hp.x = h0; hp.y = h1;
    __nv_bfloat162 lp; lp.x = l0; lp.y = l1;
    g_xh2[idx] = *reinterpret_cast<u32*>(&hp);
    g_xl2[idx] = *reinterpret_cast<u32*>(&lp);
}

// ---------------- conv bank on HMMA (unchanged, passing) ----------
#define CAP 132
#define SM_AL 9240
#define SM_B  18480
#define SM_CONV_U32 (18480 + 32768)
#define B_CHUNKS 4096
__global__ void __launch_bounds__(256, 1) k_conv_mma(
    const float* __restrict__ bconv, int iter)
{
    extern __shared__ u32 sm[];
    u32* Ah = sm;
    u32* Al = sm + SM_AL;
    u32* Bb = sm + SM_B;

    const int tid  = threadIdx.x;
    const int warp = tid >> 5, lane = tid & 31;
    const int gid  = lane >> 2, tg = lane & 3;
    const int b    = blockIdx.x >> 3;
    const int t0   = (blockIdx.x & 7) * 64;
    const int n0   = blockIdx.y * 64;
    const int wm   = (warp & 3) * 16;
    const int wn   = (warp >> 2) * 32;

    for (int idx = tid; idx < 70 * 128; idx += 256) {
        int r = idx >> 7, c = idx & 127;
        int t = t0 - 3 + r;
        u32 vh = 0, vl = 0;
        if (t >= 0 && t < TSEQ) {
            size_t g = ((size_t)b * TSEQ + t) * 128 + c;
            vh = g_xh2[g]; vl = g_xl2[g];
        }
        Ah[r * CAP + c] = vh;
        Al[r * CAP + c] = vl;
    }

    const size_t wbase = (size_t)(iter * 15) * 2 * 32768;
    {
        for (int i = tid; i < B_CHUNKS; i += 256) {
            int p = i >> 11, rem = i & 2047;
            int n = rem >> 5, cq = rem & 31;
            int c0 = cq * 4;
            u32 dsw = (u32)c0 ^ (((u32)n & 7) << 2);
            u32 dst = smem_u32addr(Bb + p * 8192 + n * 128 + dsw);
            const u32* src = g_Wb2 + wbase + (size_t)p * 32768 + (size_t)(n0 + n) * 128 + c0;
            cp_async16(dst, src);
        }
        CP_COMMIT();
    }
    CP_WAIT0();
    __syncthreads();

    float acc[3][4][4];
#pragma unroll
    for (int w = 0; w < 3; ++w)
#pragma unroll
        for (int j = 0; j < 4; ++j)
#pragma unroll
            for (int q = 0; q < 4; ++q) acc[w][j][q] = 0.f;

    for (int tap = 0; tap < 15; ++tap) {
        int widx, kk;
        if (tap < 3)      { widx = 0; kk = tap; }
        else if (tap < 8) { widx = 1; kk = tap - 3; }
        else              { widx = 2; kk = tap - 8; }
        const int shift = kk - widx - 1;
        const int buf = tap & 1;

        if (tap < 14) {
            const size_t nb = (size_t)((iter * 15 + tap + 1) * 2) * 32768;
            u32* Bo = Bb + (buf ^ 1) * 16384;
            for (int i = tid; i < B_CHUNKS; i += 256) {
                int p = i >> 11, rem = i & 2047;
                int n = rem >> 5, cq = rem & 31;
                int c0 = cq * 4;
                u32 dsw = (u32)c0 ^ (((u32)n & 7) << 2);
                u32 dst = smem_u32addr(Bo + p * 8192 + n * 128 + dsw);
                const u32* src = g_Wb2 + nb + (size_t)p * 32768 + (size_t)(n0 + n) * 128 + c0;
                cp_async16(dst, src);
            }
            CP_COMMIT();
        }

        const u32* Bh = Bb + buf * 16384;
        const u32* Bl = Bh + 8192;
        const int r0 = 3 + shift + wm + gid;
        const u32* arh0 = Ah + r0 * CAP;
        const u32* arh1 = arh0 + 8 * CAP;
        const u32* arl0 = Al + r0 * CAP;
        const u32* arl1 = arl0 + 8 * CAP;
        float* accw = &acc[widx][0][0];

#pragma unroll
        for (int ks = 0; ks < 16; ++ks) {
            const int kc2 = ks * 8;
            u32 ah0 = arh0[kc2 + tg],     ah1 = arh1[kc2 + tg];
            u32 ah2 = arh0[kc2 + tg + 4], ah3 = arh1[kc2 + tg + 4];
            u32 al0 = arl0[kc2 + tg],     al1 = arl1[kc2 + tg];
            u32 al2 = arl0[kc2 + tg + 4], al3 = arl1[kc2 + tg + 4];
#pragma unroll
            for (int j8 = 0; j8 < 4; ++j8) {
                int nl = wn + j8 * 8 + gid;
                u32 xr = ((u32)(nl & 7)) << 2;
                const u32* bhp = Bh + nl * 128;
                const u32* blp = Bl + nl * 128;
                u32 bh0 = bhp[(kc2 + tg) ^ xr];
                u32 bh1 = bhp[(kc2 + tg + 4) ^ xr];
                u32 bl0 = blp[(kc2 + tg) ^ xr];
                u32 bl1 = blp[(kc2 + tg + 4) ^ xr];
                float* cc = accw + j8 * 4;
                mma_bf16(cc, ah0, ah1, ah2, ah3, bh0, bh1);
                mma_bf16(cc, ah0, ah1, ah2, ah3, bl0, bl1);
                mma_bf16(cc, al0, al1, al2, al3, bh0, bh1);
            }
        }

        if (tap < 14) {
            CP_WAIT0();
            __syncthreads();
        }
    }

    {
        const float* b3 = bconv + (iter * 3 + 0) * 256 + n0;
        const float* b5 = bconv + (iter * 3 + 1) * 256 + n0;
        const float* b7 = bconv + (iter * 3 + 2) * 256 + n0;
        const int trow = t0 + wm + gid;
#pragma unroll
        for (int j8 = 0; j8 < 4; ++j8) {
            int cl = wn + j8 * 8 + tg * 2;
            float bb3a = b3[cl], bb3b = b3[cl + 1];
            float bb5a = b5[cl], bb5b = b5[cl + 1];
            float bb7a = b7[cl], bb7b = b7[cl + 1];
#pragma unroll
            for (int rh = 0; rh < 2; ++rh) {
                size_t row = (size_t)b * TSEQ + trow + rh * 8;
                const float2 xv = *reinterpret_cast<const float2*>(
                    g_x + row * 256 + n0 + cl);
                float c3a = acc[0][j8][rh * 2 + 0], c3b = acc[0][j8][rh * 2 + 1];
                float c5a = acc[1][j8][rh * 2 + 0], c5b = acc[1][j8][rh * 2 + 1];
                float c7a = acc[2][j8][rh * 2 + 0], c7b = acc[2][j8][rh * 2 + 1];
                float2 o;
                o.x = tanha(c3a + bb3a) + tanha(c5a + bb5a) + tanha(c7a + bb7a) + xv.x;
                o.y = tanha(c3b + bb3b) + tanha(c5b + bb5b) + tanha(c7b + bb7b) + xv.y;
                *reinterpret_cast<float2*>(g_feats + row * 256 + n0 + cl) = o;
            }
        }
    }
}

// ---------------- layernorm ----------------
__global__ void k_ln(const float* __restrict__ gamma, const float* __restrict__ beta, int iter) {
    int wid = threadIdx.x >> 5, lane = threadIdx.x & 31;
    int row = blockIdx.x * 8 + wid;
    const float4* f = reinterpret_cast<const float4*>(g_feats + (size_t)row * DD);
    float4 v0 = f[lane];
    float4 v1 = f[32 + lane];
    float s = v0.x + v0.y + v0.z + v0.w + v1.x + v1.y + v1.z + v1.w;
    float q = v0.x*v0.x + v0.y*v0.y + v0.z*v0.z + v0.w*v0.w +
              v1.x*v1.x + v1.y*v1.y + v1.z*v1.z + v1.w*v1.w;
#pragma unroll
    for (int ofs = 16; ofs; ofs >>= 1) {
        s += __shfl_xor_sync(0xffffffffu, s, ofs);
        q += __shfl_xor_sync(0xffffffffu, q, ofs);
    }
    float mean = s * (1.f / 256.f);
    float var  = q * (1.f / 256.f) - mean * mean;
    float rstd = rsqrtf(var + 1e-3f);

    const float* ga = gamma + iter * DD;
    const float* be = beta + iter * DD;
    float4* xo = reinterpret_cast<float4*>(g_x + (size_t)row * DD);
    int c0 = lane * 4;
    float4 r0, r1;
    r0.x = (v0.x - mean) * rstd * ga[c0 + 0] + be[c0 + 0];
    r0.y = (v0.y - mean) * rstd * ga[c0 + 1] + be[c0 + 1];
    r0.z = (v0.z - mean) * rstd * ga[c0 + 2] + be[c0 + 2];
    r0.w = (v0.w - mean) * rstd * ga[c0 + 3] + be[c0 + 3];
    r1.x = (v1.x - mean) * rstd * ga[128 + c0 + 0] + be[128 + c0 + 0];
    r1.y = (v1.y - mean) * rstd * ga[128 + c0 + 1] + be[128 + c0 + 1];
    r1.z = (v1.z - mean) * rstd * ga[128 + c0 + 2] + be[128 + c0 + 2];
    r1.w = (v1.w - mean) * rstd * ga[128 + c0 + 3] + be[128 + c0 + 3];
    xo[lane] = r0;
    xo[32 + lane] = r1;
}

__global__ void k_zero() {
    int i = blockIdx.x * 256 + threadIdx.x;
    if (i < 196608) {
        reinterpret_cast<u32*>(g_hbh)[i] = 0u;
        reinterpret_cast<u32*>(g_hbl)[i] = 0u;
    }
    if (i == 0) g_sync = 0u;
}

// ---------------- persistent wavefront LSTM on HMMA ------------------------
// 96 blocks x 512 threads (4 warps/SMSP). 16 warps: tile 16m x 32n each
// (mgrp = warp&7 -> m0 = mgrp*16; ngrp = warp>>3 -> n-half).
#define LAP 36
#define LSTM_SMEM_U32 (32768 + 2 * 2 * 128 * LAP)
__global__ void __launch_bounds__(512, 1) k_lstm_mma(
    const float* __restrict__ blstm, float* __restrict__ out)
{
    extern __shared__ u32 sm[];
    u32* Bs = sm;
    u32* As = sm + 32768;

    const int bx    = blockIdx.x;
    const int ls    = bx >> 4;
    const int dir   = ls & 1;
    const int layer = ls >> 1;
    const int sub   = bx & 15;
    const int j0    = sub * 16;
    const int tid   = threadIdx.x;
    const int warp  = tid >> 5, lane = tid & 31;
    const int gid   = lane >> 2, tg = lane & 3;
    const int mgrp  = warp & 7;          // 8 m-groups of 16 rows
    const int ngrp  = warp >> 3;         // 2 n-groups of 32
    const int m0    = mgrp * 16;
    const int dl    = dir * 3 + layer;

    for (int i = tid; i < 8192; i += 512) {
        int plane = i >> 12, rem = i & 4095;
        int n = rem >> 6, c0 = (rem & 63) * 4;
        u32 dsw = (u32)c0 ^ (((u32)n & 7) << 2);
        u32 dst = smem_u32addr(Bs + plane * 16384 + n * 256 + dsw);
        const __nv_bfloat16* src = g_Wlb +
            ((size_t)(plane * 6 + dl) * 1024 + (j0 * 4 + n)) * 512 + c0 * 2;
        cp_async16(dst, src);
    }
    CP_COMMIT();

    // per-thread constants: 4 cols
    float bias[4][4];
    float creg[4];
#pragma unroll
    for (int j4 = 0; j4 < 4; ++j4) {
        int cg = j0 + 2 * (ngrp * 4 + j4) + (tg >> 1);
        bias[j4][0] = blstm[dl * NG + 0 * 256 + cg];
        bias[j4][1] = blstm[dl * NG + 1 * 256 + cg];
        bias[j4][2] = blstm[dl * NG + 2 * 256 + cg];
        bias[j4][3] = blstm[dl * NG + 3 * 256 + cg];
        creg[j4] = 0.f;
    }
    const int ftm = tid >> 2;            // 0..127 row
    const int fko = (tid & 3) * 16;      // bf16 k offset within 64-k chunk
    const int mrow = m0 + gid + ((tg & 1) ? 8 : 0);

    CP_WAIT0();
    __syncthreads();

    const unsigned nb = gridDim.x;
    const int lprev = (layer > 0) ? (layer - 1) : 0;
    const __nv_bfloat16* gxh = reinterpret_cast<const __nv_bfloat16*>(g_xh2);
    const __nv_bfloat16* gxl = reinterpret_cast<const __nv_bfloat16*>(g_xl2);

    for (int w = 0; w < TSEQ + 2; ++w) {
        const int t = w - layer;
        if (t >= 0 && t < TSEQ) {
            const int tt = dir ? (TSEQ - 1 - t) : t;
            const int rp = t & 1, wp = rp ^ 1;
            const int par = t & 1;
            const size_t curoffR = (size_t)((dir * 2 + lprev) * 2 + par) * BB * 256;
            const size_t curoffW = (size_t)((dir * 2 + layer) * 2 + par) * BB * 256;
            const size_t hoffR   = (size_t)(dl * 2 + rp) * BB * 256;
            const size_t hoffW   = (size_t)(dl * 2 + wp) * BB * 256;

            const __nv_bfloat16 *lowh, *lowl;
            if (layer == 0) {
                lowh = gxh + ((size_t)ftm * TSEQ + tt) * 256;
                lowl = gxl + ((size_t)ftm * TSEQ + tt) * 256;
            } else {
                lowh = g_cbh + curoffR + (size_t)ftm * 256;
                lowl = g_cbl + curoffR + (size_t)ftm * 256;
            }
            const __nv_bfloat16* hh_ = g_hbh + hoffR + (size_t)ftm * 256;
            const __nv_bfloat16* hl_ = g_hbl + hoffR + (size_t)ftm * 256;

            // residual prefetch (1 m-row x 4 cols)
            float ainv[4];
#pragma unroll
            for (int j4 = 0; j4 < 4; ++j4) {
                int cg = j0 + 2 * (ngrp * 4 + j4) + (tg >> 1);
                if (layer == 0) {
                    size_t xi = ((size_t)mrow * TSEQ + tt) * 256 + cg;
                    ainv[j4] = __bfloat162float(gxh[xi]) + __bfloat162float(gxl[xi]);
                } else {
                    size_t ci = curoffR + (size_t)mrow * 256 + cg;
                    ainv[j4] = __bfloat162float(__ldcg(g_cbh + ci)) +
                               __bfloat162float(__ldcg(g_cbl + ci));
                }
            }

            float acc[4][4];
#pragma unroll
            for (int j4 = 0; j4 < 4; ++j4)
#pragma unroll
                for (int q = 0; q < 4; ++q) acc[j4][q] = 0.f;

#define STAGE(ci_, buf_) do {                                              \
    int kb_ = (ci_) * 64 + fko;                                            \
    const __nv_bfloat16 *sh_, *sl_;                                        \
    if (kb_ < 256) { sh_ = lowh + kb_; sl_ = lowl + kb_; }                 \
    else           { sh_ = hh_ + (kb_ - 256); sl_ = hl_ + (kb_ - 256); }   \
    u32 db_ = (buf_) * (2 * 128 * LAP) + ftm * LAP + (fko >> 1);           \
    _Pragma("unroll")                                                      \
    for (int j_ = 0; j_ < 2; ++j_)                                         \
        cp_async16(smem_u32addr(As + db_ + j_ * 4), sh_ + j_ * 8);         \
    db_ += 128 * LAP;                                                      \
    _Pragma("unroll")                                                      \
    for (int j_ = 0; j_ < 2; ++j_)                                         \
        cp_async16(smem_u32addr(As + db_ + j_ * 4), sl_ + j_ * 8);         \
} while (0)

            STAGE(0, 0); CP_COMMIT(); CP_WAIT0(); __syncthreads();

            for (int ci = 0; ci < 8; ++ci) {
                if (ci < 7) { STAGE(ci + 1, (ci + 1) & 1); CP_COMMIT(); }

                const u32* AhB = As + (ci & 1) * (2 * 128 * LAP);
                const u32* AlB = AhB + 128 * LAP;
                const int ra = (m0 + gid) * LAP;
                const int rb = ra + 8 * LAP;
#pragma unroll
                for (int ks = 0; ks < 4; ++ks) {
                    const int pk = ks * 8 + tg;
                    const int kp = ci * 32 + pk;
                    u32 ah0 = AhB[ra + pk],     ah1 = AhB[rb + pk];
                    u32 ah2 = AhB[ra + pk + 4], ah3 = AhB[rb + pk + 4];
                    u32 al0 = AlB[ra + pk],     al1 = AlB[rb + pk];
                    u32 al2 = AlB[ra + pk + 4], al3 = AlB[rb + pk + 4];
#pragma unroll
                    for (int j4 = 0; j4 < 4; ++j4) {
                        int nl = ngrp * 32 + j4 * 8 + gid;
                        u32 xr = (u32)(nl & 7) << 2;
                        const u32* bh = Bs + nl * 256;
                        const u32* bl = bh + 16384;
                        u32 b0h = bh[kp ^ xr], b1h = bh[(kp + 4) ^ xr];
                        u32 b0l = bl[kp ^ xr], b1l = bl[(kp + 4) ^ xr];
                        mma_bf16(acc[j4], ah0, ah1, ah2, ah3, b0h, b1h);
                        mma_bf16(acc[j4], ah0, ah1, ah2, ah3, b0l, b1l);
                        mma_bf16(acc[j4], al0, al1, al2, al3, b0h, b1h);
                    }
                }
                if (ci < 7) { CP_WAIT0(); __syncthreads(); }
            }
#undef STAGE

            // ---- epilogue ----
#pragma unroll
            for (int j4 = 0; j4 < 4; ++j4) {
                float c0 = acc[j4][0], c1 = acc[j4][1];
                float c2 = acc[j4][2], c3 = acc[j4][3];
                float sendA = (tg & 1) ? c0 : c2;
                float sendB = (tg & 1) ? c1 : c3;
                float rA = __shfl_xor_sync(0xffffffffu, sendA, 1);
                float rB = __shfl_xor_sync(0xffffffffu, sendB, 1);
                float zi, zf, zg, zo;
                if (!(tg & 1)) { zi = c0; zf = c1; zg = rA; zo = rB; }
                else           { zi = rA; zf = rB; zg = c2; zo = c3; }
                zi += bias[j4][0]; zf += bias[j4][1];
                zg += bias[j4][2]; zo += bias[j4][3];
                float ig = sigm(zi);
                float fg = sigm(zf);
                float gg = tanha(zg);
                float og = sigm(zo);
                float cn = fg * creg[j4] + ig * gg;
                float hn = og * tanha(cn);
                creg[j4] = cn;
                int cg = j0 + 2 * (ngrp * 4 + j4) + (tg >> 1);
                size_t hidx = hoffW + (size_t)mrow * 256 + cg;
                __nv_bfloat16 hh2 = __float2bfloat16(hn);
                g_hbh[hidx] = hh2;
                g_hbl[hidx] = __float2bfloat16(hn - __bfloat162float(hh2));
                if (t == TSEQ - 1) {
                    g_h[(size_t)(dl * 2 + wp) * BB * HH + (size_t)mrow * HH + cg] = hn;
                    g_c[(size_t)dl * BB * HH + (size_t)mrow * HH + cg] = cn;
                }
                float cu = ainv[j4] + hn;
                if (layer == 2) {
                    out[((size_t)mrow * TSEQ + tt) * 512 + dir * 256 + cg] = cu;
                } else {
                    size_t cidx = curoffW + (size_t)mrow * 256 + cg;
                    __nv_bfloat16 ch2 = __float2bfloat16(cu);
                    g_cbh[cidx] = ch2;
                    g_cbl[cidx] = __float2bfloat16(cu - __bfloat162float(ch2));
                }
            }
        }

        // ---- grid barrier ----
        __syncthreads();
        __threadfence();
        if (tid == 0) {
            atomicAdd(&g_sync, 1u);
            unsigned target = nb * (unsigned)(w + 1);
            while (*(volatile unsigned*)&g_sync < target) __nanosleep(64);
        }
        __syncthreads();
    }
}

// ---------------- final states ----------------
__global__ void k_states(float* __restrict__ out) {
    int idx = blockIdx.x * 256 + threadIdx.x;
    if (idx >= 2 * 3 * BB * HH) return;
    int j  = idx & 255;
    int m  = (idx >> 8) & 127;
    int dl = idx >> 15;
    const size_t SEQ = (size_t)BB * TSEQ * 512;
    const size_t SH  = 2 * 3 * BB * HH;
    out[SEQ + idx]      = g_h[(size_t)(dl * 2 + 0) * BB * HH + (size_t)m * HH + j];
    out[SEQ + SH + idx] = g_c[(size_t)dl * BB * HH + (size_t)m * HH + j];
}

// ---------------- launch ----------------
extern "C" void kernel_launch(void* const* d_in, const int* in_sizes, int n_in,
                              void* d_out, int out_size) {
    const int*   tokens = (const int*)d_in[0];
    const float* E      = (const float*)d_in[1];
    const float* W3     = (const float*)d_in[2];
    const float* W5     = (const float*)d_in[3];
    const float* W7     = (const float*)d_in[4];
    const float* bconv  = (const float*)d_in[5];
    const float* gamma  = (const float*)d_in[6];
    const float* beta   = (const float*)d_in[7];
    const float* Wx     = (const float*)d_in[8];
    const float* Wh     = (const float*)d_in[9];
    const float* blstm  = (const float*)d_in[10];
    float* out = (float*)d_out;

    const int SMEM_CONV = SM_CONV_U32 * 4;
    const int SMEM_LSTM = LSTM_SMEM_U32 * 4;
    static int s_attr = 0;
    if (!s_attr) {
        cudaFuncSetAttribute(k_conv_mma,
                             cudaFuncAttributeMaxDynamicSharedMemorySize, SMEM_CONV);
        cudaFuncSetAttribute(k_lstm_mma,
                             cudaFuncAttributeMaxDynamicSharedMemorySize, SMEM_LSTM);
        s_attr = 1;
    }

    k_embed<<<BB * TSEQ, 64>>>(tokens, E);
    k_wprep<<<(2 * 15 * 2 * 65536 + 255) / 256, 256>>>(W3, W5, W7);
    k_wprep_lstm<<<(int)((2ull * 6 * 1024 * 512 + 255) / 256), 256>>>(Wx, Wh);
    for (int it = 0; it < 2; ++it) {
        k_xsplit<<<(BB * TSEQ * 128) / 256, 256>>>();
        k_conv_mma<<<dim3(BB * 8, 4), 256, SMEM_CONV>>>(bconv, it);
        k_ln<<<BB * TSEQ / 8, 256>>>(gamma, beta, it);
    }
    k_xsplit<<<(BB * TSEQ * 128) / 256, 256>>>();
    k_zero<<<1536, 256>>>();
    k_lstm_mma<<<NBLK, 512, SMEM_LSTM>>>(blstm, out);
    k_states<<<768, 256>>>(out);
}

// round 16
// speedup vs baseline: 2.3603x; 1.0381x over previous
#include <cuda_runtime.h>
#include <cuda_bf16.h>
#include <math.h>
#include <cstdint>

#define BB   128
#define TSEQ 512
#define DD   256
#define HH   256
#define NG   1024
#define NBLK 96

typedef unsigned long long u64;
typedef unsigned int u32;

// ---- warp-level bf16 MMA (verified R11/R12) ----
__device__ __forceinline__ void mma_bf16(float* c, u32 a0, u32 a1, u32 a2, u32 a3,
                                         u32 b0, u32 b1) {
    asm volatile(
        "mma.sync.aligned.m16n8k16.row.col.f32.bf16.bf16.f32 "
        "{%0,%1,%2,%3}, {%4,%5,%6,%7}, {%8,%9}, {%0,%1,%2,%3};"
        : "+f"(c[0]), "+f"(c[1]), "+f"(c[2]), "+f"(c[3])
        : "r"(a0), "r"(a1), "r"(a2), "r"(a3), "r"(b0), "r"(b1));
}
__device__ __forceinline__ u32 smem_u32addr(const void* p) {
    u32 a;
    asm("{ .reg .u64 t; cvta.to.shared.u64 t, %1; cvt.u32.u64 %0, t; }" : "=r"(a) : "l"(p));
    return a;
}
__device__ __forceinline__ void cp_async16(u32 dst, const void* src) {
    asm volatile("cp.async.cg.shared.global [%0], [%1], 16;" :: "r"(dst), "l"(src));
}
#define CP_COMMIT() asm volatile("cp.async.commit_group;" ::: "memory")
#define CP_WAIT0()  asm volatile("cp.async.wait_group 0;" ::: "memory")
__device__ __forceinline__ float tanha(float x) {
    float r; asm("tanh.approx.f32 %0, %1;" : "=f"(r) : "f"(x)); return r;
}
__device__ __forceinline__ float sigm(float x) {
    return 0.5f + 0.5f * tanha(0.5f * x);
}

// ---------------- device scratch ----------------
__device__ float g_x[BB * TSEQ * DD];
__device__ float g_feats[BB * TSEQ * DD];
__device__ float g_h[2 * 3 * 2 * BB * HH];
__device__ float g_c[2 * 3 * BB * HH];
__device__ unsigned g_sync;
__device__ u32 g_xh2[BB * TSEQ * 128];
__device__ u32 g_xl2[BB * TSEQ * 128];
__device__ u32 g_Wb2[2 * 15 * 2 * 32768];
__device__ __nv_bfloat16 g_Wlb[2ull * 6 * 1024 * 512];
__device__ __nv_bfloat16 g_hbh[6 * 2 * BB * 256];
__device__ __nv_bfloat16 g_hbl[6 * 2 * BB * 256];
__device__ __nv_bfloat16 g_cbh[2 * 2 * 2 * BB * 256];
__device__ __nv_bfloat16 g_cbl[2 * 2 * 2 * BB * 256];

// ---------------- embedding gather ----------------
__global__ void k_embed(const int* __restrict__ tokens, const float* __restrict__ E) {
    int row = blockIdx.x;
    int tok = tokens[row];
    const float4* src = reinterpret_cast<const float4*>(E) + (size_t)tok * (DD / 4);
    float4* dst = reinterpret_cast<float4*>(g_x) + (size_t)row * (DD / 4);
    dst[threadIdx.x] = src[threadIdx.x];
}

// ---------------- conv W pack ----------------
__global__ void k_wprep(const float* __restrict__ W3, const float* __restrict__ W5,
                        const float* __restrict__ W7) {
    int idx = blockIdx.x * 256 + threadIdx.x;
    const int TOT = 2 * 15 * 2 * 65536;
    if (idx >= TOT) return;
    int k     = idx & 255;
    int n     = (idx >> 8) & 255;
    int plane = (idx >> 16) & 1;
    int tp    = idx >> 17;
    int tap   = tp % 15;
    int iter  = tp / 15;
    const float* Wsrc; int kk, KW;
    if (tap < 3)      { Wsrc = W3; kk = tap;     KW = 3; }
    else if (tap < 8) { Wsrc = W5; kk = tap - 3; KW = 5; }
    else              { Wsrc = W7; kk = tap - 8; KW = 7; }
    float v = Wsrc[(((size_t)iter * KW + kk) * 256 + k) * 256 + n];
    __nv_bfloat16 hi = __float2bfloat16(v);
    __nv_bfloat16 val = plane ? __float2bfloat16(v - __bfloat162float(hi)) : hi;
    __nv_bfloat16* dst = reinterpret_cast<__nv_bfloat16*>(g_Wb2);
    dst[(size_t)(((iter * 15 + tap) * 2 + plane)) * 65536 + n * 256 + k] = val;
}

// ---------------- LSTM W pack ----------
__global__ void k_wprep_lstm(const float* __restrict__ Wx, const float* __restrict__ Wh) {
    size_t idx = (size_t)blockIdx.x * 256 + threadIdx.x;
    const size_t TOT = 2ull * 6 * 1024 * 512;
    if (idx >= TOT) return;
    int k     = (int)(idx & 511);
    int n     = (int)((idx >> 9) & 1023);
    int dl    = (int)((idx >> 19) % 6);
    int plane = (int)(idx / (6ull << 19));
    int col = n >> 2, g = n & 3;
    int nc = g * 256 + col;
    float v = (k < 256) ? Wx[(size_t)dl * 256 * NG + (size_t)k * NG + nc]
                        : Wh[(size_t)dl * 256 * NG + (size_t)(k - 256) * NG + nc];
    __nv_bfloat16 hi = __float2bfloat16(v);
    __nv_bfloat16 val = plane ? __float2bfloat16(v - __bfloat162float(hi)) : hi;
    g_Wlb[idx] = val;
}

// ---------------- x split ----------
__global__ void k_xsplit() {
    size_t idx = (size_t)blockIdx.x * 256 + threadIdx.x;
    float a0 = g_x[idx * 2], a1 = g_x[idx * 2 + 1];
    __nv_bfloat16 h0 = __float2bfloat16(a0), h1 = __float2bfloat16(a1);
    __nv_bfloat16 l0 = __float2bfloat16(a0 - __bfloat162float(h0));
    __nv_bfloat16 l1 = __float2bfloat16(a1 - __bfloat162float(h1));
    __nv_bfloat162 hp; hp.x = h0; hp.y = h1;
    __nv_bfloat162 lp; lp.x = l0; lp.y = l1;
    g_xh2[idx] = *reinterpret_cast<u32*>(&hp);
    g_xl2[idx] = *reinterpret_cast<u32*>(&lp);
}

// ---------------- conv bank on HMMA (unchanged, passing) ----------
#define CAP 132
#define SM_AL 9240
#define SM_B  18480
#define SM_CONV_U32 (18480 + 32768)
#define B_CHUNKS 4096
__global__ void __launch_bounds__(256, 1) k_conv_mma(
    const float* __restrict__ bconv, int iter)
{
    extern __shared__ u32 sm[];
    u32* Ah = sm;
    u32* Al = sm + SM_AL;
    u32* Bb = sm + SM_B;

    const int tid  = threadIdx.x;
    const int warp = tid >> 5, lane = tid & 31;
    const int gid  = lane >> 2, tg = lane & 3;
    const int b    = blockIdx.x >> 3;
    const int t0   = (blockIdx.x & 7) * 64;
    const int n0   = blockIdx.y * 64;
    const int wm   = (warp & 3) * 16;
    const int wn   = (warp >> 2) * 32;

    for (int idx = tid; idx < 70 * 128; idx += 256) {
        int r = idx >> 7, c = idx & 127;
        int t = t0 - 3 + r;
        u32 vh = 0, vl = 0;
        if (t >= 0 && t < TSEQ) {
            size_t g = ((size_t)b * TSEQ + t) * 128 + c;
            vh = g_xh2[g]; vl = g_xl2[g];
        }
        Ah[r * CAP + c] = vh;
        Al[r * CAP + c] = vl;
    }

    const size_t wbase = (size_t)(iter * 15) * 2 * 32768;
    {
        for (int i = tid; i < B_CHUNKS; i += 256) {
            int p = i >> 11, rem = i & 2047;
            int n = rem >> 5, cq = rem & 31;
            int c0 = cq * 4;
            u32 dsw = (u32)c0 ^ (((u32)n & 7) << 2);
            u32 dst = smem_u32addr(Bb + p * 8192 + n * 128 + dsw);
            const u32* src = g_Wb2 + wbase + (size_t)p * 32768 + (size_t)(n0 + n) * 128 + c0;
            cp_async16(dst, src);
        }
        CP_COMMIT();
    }
    CP_WAIT0();
    __syncthreads();

    float acc[3][4][4];
#pragma unroll
    for (int w = 0; w < 3; ++w)
#pragma unroll
        for (int j = 0; j < 4; ++j)
#pragma unroll
            for (int q = 0; q < 4; ++q) acc[w][j][q] = 0.f;

    for (int tap = 0; tap < 15; ++tap) {
        int widx, kk;
        if (tap < 3)      { widx = 0; kk = tap; }
        else if (tap < 8) { widx = 1; kk = tap - 3; }
        else              { widx = 2; kk = tap - 8; }
        const int shift = kk - widx - 1;
        const int buf = tap & 1;

        if (tap < 14) {
            const size_t nb = (size_t)((iter * 15 + tap + 1) * 2) * 32768;
            u32* Bo = Bb + (buf ^ 1) * 16384;
            for (int i = tid; i < B_CHUNKS; i += 256) {
                int p = i >> 11, rem = i & 2047;
                int n = rem >> 5, cq = rem & 31;
                int c0 = cq * 4;
                u32 dsw = (u32)c0 ^ (((u32)n & 7) << 2);
                u32 dst = smem_u32addr(Bo + p * 8192 + n * 128 + dsw);
                const u32* src = g_Wb2 + nb + (size_t)p * 32768 + (size_t)(n0 + n) * 128 + c0;
                cp_async16(dst, src);
            }
            CP_COMMIT();
        }

        const u32* Bh = Bb + buf * 16384;
        const u32* Bl = Bh + 8192;
        const int r0 = 3 + shift + wm + gid;
        const u32* arh0 = Ah + r0 * CAP;
        const u32* arh1 = arh0 + 8 * CAP;
        const u32* arl0 = Al + r0 * CAP;
        const u32* arl1 = arl0 + 8 * CAP;
        float* accw = &acc[widx][0][0];

#pragma unroll
        for (int ks = 0; ks < 16; ++ks) {
            const int kc2 = ks * 8;
            u32 ah0 = arh0[kc2 + tg],     ah1 = arh1[kc2 + tg];
            u32 ah2 = arh0[kc2 + tg + 4], ah3 = arh1[kc2 + tg + 4];
            u32 al0 = arl0[kc2 + tg],     al1 = arl1[kc2 + tg];
            u32 al2 = arl0[kc2 + tg + 4], al3 = arl1[kc2 + tg + 4];
#pragma unroll
            for (int j8 = 0; j8 < 4; ++j8) {
                int nl = wn + j8 * 8 + gid;
                u32 xr = ((u32)(nl & 7)) << 2;
                const u32* bhp = Bh + nl * 128;
                const u32* blp = Bl + nl * 128;
                u32 bh0 = bhp[(kc2 + tg) ^ xr];
                u32 bh1 = bhp[(kc2 + tg + 4) ^ xr];
                u32 bl0 = blp[(kc2 + tg) ^ xr];
                u32 bl1 = blp[(kc2 + tg + 4) ^ xr];
                float* cc = accw + j8 * 4;
                mma_bf16(cc, ah0, ah1, ah2, ah3, bh0, bh1);
                mma_bf16(cc, ah0, ah1, ah2, ah3, bl0, bl1);
                mma_bf16(cc, al0, al1, al2, al3, bh0, bh1);
            }
        }

        if (tap < 14) {
            CP_WAIT0();
            __syncthreads();
        }
    }

    {
        const float* b3 = bconv + (iter * 3 + 0) * 256 + n0;
        const float* b5 = bconv + (iter * 3 + 1) * 256 + n0;
        const float* b7 = bconv + (iter * 3 + 2) * 256 + n0;
        const int trow = t0 + wm + gid;
#pragma unroll
        for (int j8 = 0; j8 < 4; ++j8) {
            int cl = wn + j8 * 8 + tg * 2;
            float bb3a = b3[cl], bb3b = b3[cl + 1];
            float bb5a = b5[cl], bb5b = b5[cl + 1];
            float bb7a = b7[cl], bb7b = b7[cl + 1];
#pragma unroll
            for (int rh = 0; rh < 2; ++rh) {
                size_t row = (size_t)b * TSEQ + trow + rh * 8;
                const float2 xv = *reinterpret_cast<const float2*>(
                    g_x + row * 256 + n0 + cl);
                float c3a = acc[0][j8][rh * 2 + 0], c3b = acc[0][j8][rh * 2 + 1];
                float c5a = acc[1][j8][rh * 2 + 0], c5b = acc[1][j8][rh * 2 + 1];
                float c7a = acc[2][j8][rh * 2 + 0], c7b = acc[2][j8][rh * 2 + 1];
                float2 o;
                o.x = tanha(c3a + bb3a) + tanha(c5a + bb5a) + tanha(c7a + bb7a) + xv.x;
                o.y = tanha(c3b + bb3b) + tanha(c5b + bb5b) + tanha(c7b + bb7b) + xv.y;
                *reinterpret_cast<float2*>(g_feats + row * 256 + n0 + cl) = o;
            }
        }
    }
}

// ---------------- layernorm ----------------
__global__ void k_ln(const float* __restrict__ gamma, const float* __restrict__ beta, int iter) {
    int wid = threadIdx.x >> 5, lane = threadIdx.x & 31;
    int row = blockIdx.x * 8 + wid;
    const float4* f = reinterpret_cast<const float4*>(g_feats + (size_t)row * DD);
    float4 v0 = f[lane];
    float4 v1 = f[32 + lane];
    float s = v0.x + v0.y + v0.z + v0.w + v1.x + v1.y + v1.z + v1.w;
    float q = v0.x*v0.x + v0.y*v0.y + v0.z*v0.z + v0.w*v0.w +
              v1.x*v1.x + v1.y*v1.y + v1.z*v1.z + v1.w*v1.w;
#pragma unroll
    for (int ofs = 16; ofs; ofs >>= 1) {
        s += __shfl_xor_sync(0xffffffffu, s, ofs);
        q += __shfl_xor_sync(0xffffffffu, q, ofs);
    }
    float mean = s * (1.f / 256.f);
    float var  = q * (1.f / 256.f) - mean * mean;
    float rstd = rsqrtf(var + 1e-3f);

    const float* ga = gamma + iter * DD;
    const float* be = beta + iter * DD;
    float4* xo = reinterpret_cast<float4*>(g_x + (size_t)row * DD);
    int c0 = lane * 4;
    float4 r0, r1;
    r0.x = (v0.x - mean) * rstd * ga[c0 + 0] + be[c0 + 0];
    r0.y = (v0.y - mean) * rstd * ga[c0 + 1] + be[c0 + 1];
    r0.z = (v0.z - mean) * rstd * ga[c0 + 2] + be[c0 + 2];
    r0.w = (v0.w - mean) * rstd * ga[c0 + 3] + be[c0 + 3];
    r1.x = (v1.x - mean) * rstd * ga[128 + c0 + 0] + be[128 + c0 + 0];
    r1.y = (v1.y - mean) * rstd * ga[128 + c0 + 1] + be[128 + c0 + 1];
    r1.z = (v1.z - mean) * rstd * ga[128 + c0 + 2] + be[128 + c0 + 2];
    r1.w = (v1.w - mean) * rstd * ga[128 + c0 + 3] + be[128 + c0 + 3];
    xo[lane] = r0;
    xo[32 + lane] = r1;
}

__global__ void k_zero() {
    int i = blockIdx.x * 256 + threadIdx.x;
    if (i < 196608) {
        reinterpret_cast<u32*>(g_hbh)[i] = 0u;
        reinterpret_cast<u32*>(g_hbl)[i] = 0u;
    }
    if (i == 0) g_sync = 0u;
}

// ---------------- persistent wavefront LSTM on HMMA ------------------------
// 96 blocks x 512 threads (4 warps/SMSP). 16 warps: 16m x 32n tiles.
// Split accumulators (hi-chain / lo-chain) to break mma RAW serialization.
#define LAP 36
#define LSTM_SMEM_U32 (32768 + 2 * 2 * 128 * LAP)
__global__ void __launch_bounds__(512, 1) k_lstm_mma(
    const float* __restrict__ blstm, float* __restrict__ out)
{
    extern __shared__ u32 sm[];
    u32* Bs = sm;
    u32* As = sm + 32768;

    const int bx    = blockIdx.x;
    const int ls    = bx >> 4;
    const int dir   = ls & 1;
    const int layer = ls >> 1;
    const int sub   = bx & 15;
    const int j0    = sub * 16;
    const int tid   = threadIdx.x;
    const int warp  = tid >> 5, lane = tid & 31;
    const int gid   = lane >> 2, tg = lane & 3;
    const int mgrp  = warp & 7;
    const int ngrp  = warp >> 3;
    const int m0    = mgrp * 16;
    const int dl    = dir * 3 + layer;
    const int ci_res = j0 >> 6;          // A-chunk holding residual columns

    for (int i = tid; i < 8192; i += 512) {
        int plane = i >> 12, rem = i & 4095;
        int n = rem >> 6, c0 = (rem & 63) * 4;
        u32 dsw = (u32)c0 ^ (((u32)n & 7) << 2);
        u32 dst = smem_u32addr(Bs + plane * 16384 + n * 256 + dsw);
        const __nv_bfloat16* src = g_Wlb +
            ((size_t)(plane * 6 + dl) * 1024 + (j0 * 4 + n)) * 512 + c0 * 2;
        cp_async16(dst, src);
    }
    CP_COMMIT();

    float bias[4][4];
    float creg[4];
#pragma unroll
    for (int j4 = 0; j4 < 4; ++j4) {
        int cg = j0 + 2 * (ngrp * 4 + j4) + (tg >> 1);
        bias[j4][0] = blstm[dl * NG + 0 * 256 + cg];
        bias[j4][1] = blstm[dl * NG + 1 * 256 + cg];
        bias[j4][2] = blstm[dl * NG + 2 * 256 + cg];
        bias[j4][3] = blstm[dl * NG + 3 * 256 + cg];
        creg[j4] = 0.f;
    }
    const int ftm = tid >> 2;
    const int fko = (tid & 3) * 16;
    const int mrow = m0 + gid + ((tg & 1) ? 8 : 0);

    CP_WAIT0();
    __syncthreads();

    const unsigned nb = gridDim.x;
    const int lprev = (layer > 0) ? (layer - 1) : 0;
    const __nv_bfloat16* gxh = reinterpret_cast<const __nv_bfloat16*>(g_xh2);
    const __nv_bfloat16* gxl = reinterpret_cast<const __nv_bfloat16*>(g_xl2);

    for (int w = 0; w < TSEQ + 2; ++w) {
        const int t = w - layer;
        if (t >= 0 && t < TSEQ) {
            const int tt = dir ? (TSEQ - 1 - t) : t;
            const int rp = t & 1, wp = rp ^ 1;
            const int par = t & 1;
            const size_t curoffR = (size_t)((dir * 2 + lprev) * 2 + par) * BB * 256;
            const size_t curoffW = (size_t)((dir * 2 + layer) * 2 + par) * BB * 256;
            const size_t hoffR   = (size_t)(dl * 2 + rp) * BB * 256;
            const size_t hoffW   = (size_t)(dl * 2 + wp) * BB * 256;

            const __nv_bfloat16 *lowh, *lowl;
            if (layer == 0) {
                lowh = gxh + ((size_t)ftm * TSEQ + tt) * 256;
                lowl = gxl + ((size_t)ftm * TSEQ + tt) * 256;
            } else {
                lowh = g_cbh + curoffR + (size_t)ftm * 256;
                lowl = g_cbl + curoffR + (size_t)ftm * 256;
            }
            const __nv_bfloat16* hh_ = g_hbh + hoffR + (size_t)ftm * 256;
            const __nv_bfloat16* hl_ = g_hbl + hoffR + (size_t)ftm * 256;

            float ainv[4];
            float acc[4][4], accL[4][4];
#pragma unroll
            for (int j4 = 0; j4 < 4; ++j4)
#pragma unroll
                for (int q = 0; q < 4; ++q) { acc[j4][q] = 0.f; accL[j4][q] = 0.f; }

#define STAGE(ci_, buf_) do {                                              \
    int kb_ = (ci_) * 64 + fko;                                            \
    const __nv_bfloat16 *sh_, *sl_;                                        \
    if (kb_ < 256) { sh_ = lowh + kb_; sl_ = lowl + kb_; }                 \
    else           { sh_ = hh_ + (kb_ - 256); sl_ = hl_ + (kb_ - 256); }   \
    u32 db_ = (buf_) * (2 * 128 * LAP) + ftm * LAP + (fko >> 1);           \
    _Pragma("unroll")                                                      \
    for (int j_ = 0; j_ < 2; ++j_)                                         \
        cp_async16(smem_u32addr(As + db_ + j_ * 4), sh_ + j_ * 8);         \
    db_ += 128 * LAP;                                                      \
    _Pragma("unroll")                                                      \
    for (int j_ = 0; j_ < 2; ++j_)                                         \
        cp_async16(smem_u32addr(As + db_ + j_ * 4), sl_ + j_ * 8);         \
} while (0)

            STAGE(0, 0); CP_COMMIT(); CP_WAIT0(); __syncthreads();

            for (int ci = 0; ci < 8; ++ci) {
                if (ci < 7) { STAGE(ci + 1, (ci + 1) & 1); CP_COMMIT(); }

                const u32* AhB = As + (ci & 1) * (2 * 128 * LAP);
                const u32* AlB = AhB + 128 * LAP;
                const int ra = (m0 + gid) * LAP;
                const int rb = ra + 8 * LAP;
#pragma unroll
                for (int ks = 0; ks < 4; ++ks) {
                    const int pk = ks * 8 + tg;
                    const int kp = ci * 32 + pk;
                    u32 ah0 = AhB[ra + pk],     ah1 = AhB[rb + pk];
                    u32 ah2 = AhB[ra + pk + 4], ah3 = AhB[rb + pk + 4];
                    u32 al0 = AlB[ra + pk],     al1 = AlB[rb + pk];
                    u32 al2 = AlB[ra + pk + 4], al3 = AlB[rb + pk + 4];
#pragma unroll
                    for (int j4 = 0; j4 < 4; ++j4) {
                        int nl = ngrp * 32 + j4 * 8 + gid;
                        u32 xr = (u32)(nl & 7) << 2;
                        const u32* bh = Bs + nl * 256;
                        const u32* bl = bh + 16384;
                        u32 b0h = bh[kp ^ xr], b1h = bh[(kp + 4) ^ xr];
                        u32 b0l = bl[kp ^ xr], b1l = bl[(kp + 4) ^ xr];
                        mma_bf16(acc[j4],  ah0, ah1, ah2, ah3, b0h, b1h);  // hi*hi
                        mma_bf16(accL[j4], ah0, ah1, ah2, ah3, b0l, b1l);  // hi*lo
                        mma_bf16(acc[j4],  al0, al1, al2, al3, b0h, b1h);  // lo*hi
                    }
                }

                // residual columns live in this chunk: read from staged smem
                if (ci == ci_res) {
#pragma unroll
                    for (int j4 = 0; j4 < 4; ++j4) {
                        int cg = j0 + 2 * (ngrp * 4 + j4) + (tg >> 1);
                        int kc = cg - ci_res * 64;
                        u32 vh = AhB[mrow * LAP + (kc >> 1)];
                        u32 vl = AlB[mrow * LAP + (kc >> 1)];
                        __nv_bfloat162 bh2 = *reinterpret_cast<__nv_bfloat162*>(&vh);
                        __nv_bfloat162 bl2 = *reinterpret_cast<__nv_bfloat162*>(&vl);
                        float fh = __bfloat162float((kc & 1) ? bh2.y : bh2.x);
                        float fl = __bfloat162float((kc & 1) ? bl2.y : bl2.x);
                        ainv[j4] = fh + fl;
                    }
                }

                if (ci < 7) { CP_WAIT0(); __syncthreads(); }
            }
#undef STAGE

            // ---- epilogue ----
#pragma unroll
            for (int j4 = 0; j4 < 4; ++j4) {
                float c0 = acc[j4][0] + accL[j4][0];
                float c1 = acc[j4][1] + accL[j4][1];
                float c2 = acc[j4][2] + accL[j4][2];
                float c3 = acc[j4][3] + accL[j4][3];
                float sendA = (tg & 1) ? c0 : c2;
                float sendB = (tg & 1) ? c1 : c3;
                float rA = __shfl_xor_sync(0xffffffffu, sendA, 1);
                float rB = __shfl_xor_sync(0xffffffffu, sendB, 1);
                float zi, zf, zg, zo;
                if (!(tg & 1)) { zi = c0; zf = c1; zg = rA; zo = rB; }
                else           { zi = rA; zf = rB; zg = c2; zo = c3; }
                zi += bias[j4][0]; zf += bias[j4][1];
                zg += bias[j4][2]; zo += bias[j4][3];
                float ig = sigm(zi);
                float fg = sigm(zf);
                float gg = tanha(zg);
                float og = sigm(zo);
                float cn = fg * creg[j4] + ig * gg;
                float hn = og * tanha(cn);
                creg[j4] = cn;
                int cg = j0 + 2 * (ngrp * 4 + j4) + (tg >> 1);
                size_t hidx = hoffW + (size_t)mrow * 256 + cg;
                __nv_bfloat16 hh2 = __float2bfloat16(hn);
                g_hbh[hidx] = hh2;
                g_hbl[hidx] = __float2bfloat16(hn - __bfloat162float(hh2));
                if (t == TSEQ - 1) {
                    g_h[(size_t)(dl * 2 + wp) * BB * HH + (size_t)mrow * HH + cg] = hn;
                    g_c[(size_t)dl * BB * HH + (size_t)mrow * HH + cg] = cn;
                }
                float cu = ainv[j4] + hn;
                if (layer == 2) {
                    out[((size_t)mrow * TSEQ + tt) * 512 + dir * 256 + cg] = cu;
                } else {
                    size_t cidx = curoffW + (size_t)mrow * 256 + cg;
                    __nv_bfloat16 ch2 = __float2bfloat16(cu);
                    g_cbh[cidx] = ch2;
                    g_cbl[cidx] = __float2bfloat16(cu - __bfloat162float(ch2));
                }
            }
        }

        // ---- grid barrier (tight poll) ----
        __syncthreads();
        __threadfence();
        if (tid == 0) {
            atomicAdd(&g_sync, 1u);
            unsigned target = nb * (unsigned)(w + 1);
            while (*(volatile unsigned*)&g_sync < target) { }
        }
        __syncthreads();
    }
}

// ---------------- final states ----------------
__global__ void k_states(float* __restrict__ out) {
    int idx = blockIdx.x * 256 + threadIdx.x;
    if (idx >= 2 * 3 * BB * HH) return;
    int j  = idx & 255;
    int m  = (idx >> 8) & 127;
    int dl = idx >> 15;
    const size_t SEQ = (size_t)BB * TSEQ * 512;
    const size_t SH  = 2 * 3 * BB * HH;
    out[SEQ + idx]      = g_h[(size_t)(dl * 2 + 0) * BB * HH + (size_t)m * HH + j];
    out[SEQ + SH + idx] = g_c[(size_t)dl * BB * HH + (size_t)m * HH + j];
}

// ---------------- launch ----------------
extern "C" void kernel_launch(void* const* d_in, const int* in_sizes, int n_in,
                              void* d_out, int out_size) {
    const int*   tokens = (const int*)d_in[0];
    const float* E      = (const float*)d_in[1];
    const float* W3     = (const float*)d_in[2];
    const float* W5     = (const float*)d_in[3];
    const float* W7     = (const float*)d_in[4];
    const float* bconv  = (const float*)d_in[5];
    const float* gamma  = (const float*)d_in[6];
    const float* beta   = (const float*)d_in[7];
    const float* Wx     = (const float*)d_in[8];
    const float* Wh     = (const float*)d_in[9];
    const float* blstm  = (const float*)d_in[10];
    float* out = (float*)d_out;

    const int SMEM_CONV = SM_CONV_U32 * 4;
    const int SMEM_LSTM = LSTM_SMEM_U32 * 4;
    static int s_attr = 0;
    if (!s_attr) {
        cudaFuncSetAttribute(k_conv_mma,
                             cudaFuncAttributeMaxDynamicSharedMemorySize, SMEM_CONV);
        cudaFuncSetAttribute(k_lstm_mma,
                             cudaFuncAttributeMaxDynamicSharedMemorySize, SMEM_LSTM);
        s_attr = 1;
    }

    k_embed<<<BB * TSEQ, 64>>>(tokens, E);
    k_wprep<<<(2 * 15 * 2 * 65536 + 255) / 256, 256>>>(W3, W5, W7);
    k_wprep_lstm<<<(int)((2ull * 6 * 1024 * 512 + 255) / 256), 256>>>(Wx, Wh);
    for (int it = 0; it < 2; ++it) {
        k_xsplit<<<(BB * TSEQ * 128) / 256, 256>>>();
        k_conv_mma<<<dim3(BB * 8, 4), 256, SMEM_CONV>>>(bconv, it);
        k_ln<<<BB * TSEQ / 8, 256>>>(gamma, beta, it);
    }
    k_xsplit<<<(BB * TSEQ * 128) / 256, 256>>>();
    k_zero<<<1536, 256>>>();
    k_lstm_mma<<<NBLK, 512, SMEM_LSTM>>>(blstm, out);
    k_states<<<768, 256>>>(out);
}